// round 14
// baseline (speedup 1.0000x reference)
#include <cuda_runtime.h>
#include <cuda_fp16.h>
#include <math.h>
#include <stdint.h>

// Problem constants
#define BB   2
#define SS   2048
#define EE   2048
#define HH   16
#define KVH  4
#define DD   128
#define WINW 512
#define QKVW ((HH + 2*KVH) * DD)   // 3072
#define NROWS (BB * SS)            // 4096

// Scratch (static device globals)
__device__ __half g_qkv_h[(size_t)NROWS * QKVW];        // half qkv (pre-RoPE)
__device__ __half g_attn_h[(size_t)NROWS * HH * DD];    // attn out (half)
__device__ __half g_xh[(size_t)NROWS * EE];             // x (half) [M][K]
__device__ __half g_wqkvT_h[(size_t)QKVW * EE];         // w_qkv^T (half) [N][K]
__device__ __half g_woT_h[(size_t)EE * EE];             // w_o^T (half) [N][K]
__device__ __half g_q16[(size_t)NROWS * HH * DD];       // roped+scaled Q half
__device__ __half g_k16[(size_t)NROWS * KVH * DD];      // roped K half
__device__ __half g_vT[(size_t)BB * KVH * DD * SS];     // V half, [b][kv][d][s]

__device__ __forceinline__ uint32_t pack2h(float a, float b) {
    __half2 h = __floats2half2_rn(a, b);
    return *(uint32_t*)&h;
}

__device__ __forceinline__ void mma_f16(float* c, const uint32_t* a, const uint32_t* b) {
    asm volatile(
        "mma.sync.aligned.m16n8k16.row.col.f32.f16.f16.f32 "
        "{%0,%1,%2,%3}, {%4,%5,%6,%7}, {%8,%9}, {%0,%1,%2,%3};\n"
        : "+f"(c[0]), "+f"(c[1]), "+f"(c[2]), "+f"(c[3])
        : "r"(a[0]), "r"(a[1]), "r"(a[2]), "r"(a[3]), "r"(b[0]), "r"(b[1]));
}

__device__ __forceinline__ void ldsm4(uint32_t* d, uint32_t a) {
    asm volatile("ldmatrix.sync.aligned.m8n8.x4.shared.b16 {%0,%1,%2,%3}, [%4];"
        : "=r"(d[0]), "=r"(d[1]), "=r"(d[2]), "=r"(d[3]) : "r"(a));
}

__device__ __forceinline__ void cp_async_16(uint32_t smem_addr, const void* gptr) {
    asm volatile("cp.async.cg.shared.global [%0], [%1], 16;" :: "r"(smem_addr), "l"(gptr));
}

#define CP_COMMIT()  asm volatile("cp.async.commit_group;" ::: "memory")
#define CP_WAIT(n)   asm volatile("cp.async.wait_group %0;" :: "n"(n) : "memory")

#define SW128(b) ((b) ^ ((((uint32_t)(b)) >> 3) & 0x70))

// epilogue store helpers (overload on output type)
__device__ __forceinline__ void store2(float a, float b, float* p) {
    *(float2*)p = make_float2(a, b);
}
__device__ __forceinline__ void store2(float a, float b, __half* p) {
    *(uint32_t*)p = pack2h(a, b);
}

// ---------------------------------------------------------------------------
// Prep: fp32 -> half
// ---------------------------------------------------------------------------
__global__ void cvt_half_kernel(const float* __restrict__ in, __half* __restrict__ outp, int n4)
{
    int i = blockIdx.x * blockDim.x + threadIdx.x;
    if (i < n4) {
        float4 v = ((const float4*)in)[i];
        uint2 u;
        u.x = pack2h(v.x, v.y);
        u.y = pack2h(v.z, v.w);
        ((uint2*)outp)[i] = u;
    }
}

// in [R][C] fp32 -> out [C][R] half. 64x64 tiles, packed half2 writes
// (128B coalesced warp stores).
__global__ void __launch_bounds__(256) transpose_cvt_h64(
    const float* __restrict__ in, __half* __restrict__ outp, int R, int C)
{
    __shared__ __half t[64][66];
    const int bx = blockIdx.x * 64;   // col base (C)
    const int by = blockIdx.y * 64;   // row base (R)
    for (int idx = threadIdx.x; idx < 64 * 64; idx += 256) {
        const int row = idx >> 6, col = idx & 63;
        t[row][col] = __float2half_rn(in[(size_t)(by + row) * C + bx + col]);
    }
    __syncthreads();
    for (int idx = threadIdx.x; idx < 64 * 32; idx += 256) {
        const int orow = idx >> 5;         // output row = input col
        const int oc2  = (idx & 31) * 2;   // output col pair = input rows
        __half2 v = __halves2half2(t[oc2][orow], t[oc2 + 1][orow]);
        *(uint32_t*)&outp[(size_t)(bx + orow) * R + by + oc2] = *(uint32_t*)&v;
    }
}

// V transpose: g_qkv_h V slice [s][c] (per batch) -> vT[(b*512+c)][s]
__global__ void vtrans_kernel(const __half* __restrict__ qkv, __half* __restrict__ vT)
{
    __shared__ __half t[32][34];
    const int b  = blockIdx.z;
    const int bx = blockIdx.x * 32;   // c base
    const int by = blockIdx.y * 32;   // s base
    #pragma unroll
    for (int j = 0; j < 4; j++)
        t[threadIdx.y + j * 8][threadIdx.x] =
            qkv[(size_t)(b * SS + by + threadIdx.y + j * 8) * QKVW
                + (HH + KVH) * DD + bx + threadIdx.x];
    __syncthreads();
    #pragma unroll
    for (int j = 0; j < 4; j++)
        vT[(size_t)(b * (KVH * DD) + bx + threadIdx.y + j * 8) * SS + by + threadIdx.x] =
            t[threadIdx.x][threadIdx.y + j * 8];
}

// ---------------------------------------------------------------------------
// RoPE: fused rope + half convert, reads half qkv.
// ---------------------------------------------------------------------------
__global__ void __launch_bounds__(256) rope_cvt_kernel(
    const __half* __restrict__ qkv,
    __half* __restrict__ q16, __half* __restrict__ k16)
{
    __shared__ float cs[64], sn[64];
    const int bs = blockIdx.x;
    const int t  = threadIdx.x;
    const int s  = bs & (SS - 1);

    if (t < 64) {
        const float inv_freq = exp2f(-(float)t * 0.311430758895690262f);
        sincosf((float)s * inv_freq, &sn[t], &cs[t]);
    }
    __syncthreads();

    const __half* row = qkv + (size_t)bs * QKVW;
    const float scale = 0.088388347648318447f;  // 1/sqrt(128)

    for (int p = t; p < (HH + KVH) * 64; p += 256) {
        const int head = p >> 6;
        const int d    = p & 63;
        const __half* base = row + (head < HH ? head * DD : HH * DD + (head - HH) * DD);
        const float x0 = __half2float(base[d]);
        const float x1 = __half2float(base[d + 64]);
        const float r0 = x0 * cs[d] - x1 * sn[d];
        const float r1 = x1 * cs[d] + x0 * sn[d];
        if (head < HH) {
            __half* dst = q16 + (size_t)bs * (HH * DD) + head * DD;
            dst[d]      = __float2half_rn(r0 * scale);
            dst[d + 64] = __float2half_rn(r1 * scale);
        } else {
            __half* dst = k16 + (size_t)bs * (KVH * DD) + (head - HH) * DD;
            dst[d]      = __float2half_rn(r0);
            dst[d + 64] = __float2half_rn(r1);
        }
    }
}

// ---------------------------------------------------------------------------
// FP16 mma.sync GEMM v8 (round-12 validated): C[M,N] = A[M,K] * Bt[N,K]^T.
// CTA 128x128, 4 warps (2m x 2n), warp tile 64x64, BK=64, 3-stage cp.async,
// 96KB smem -> 2 CTAs/SM.
// ---------------------------------------------------------------------------
#define AST8  16384u
#define STG8  32768u
#define NST8  3
#define GEMM_SMEM (NST8 * STG8)      // 98304

template <typename OutT>
__global__ void __launch_bounds__(128, 2) gemm_f16_v8(
    const __half* __restrict__ A, const __half* __restrict__ Bt,
    OutT* __restrict__ C, int M, int N, int K)
{
    extern __shared__ uint32_t smu[];
    uint32_t smem_base;
    asm("{ .reg .u64 t; cvta.to.shared.u64 t, %1; cvt.u32.u64 %0, t; }"
        : "=r"(smem_base) : "l"(smu));

    const int tid    = threadIdx.x;
    const int warp   = tid >> 5;
    const int lane   = tid & 31;
    const int g      = lane >> 2;
    const int l4     = lane & 3;
    const int r      = lane & 7;
    const int q      = lane >> 3;
    const int warp_m = warp >> 1;
    const int warp_n = warp & 1;
    const int bm     = blockIdx.y * 128;
    const int bn     = blockIdx.x * 128;

    const uint32_t xr = (uint32_t)r << 4;

    uint32_t relA[4], relB[4];
    #pragma unroll
    for (int mt = 0; mt < 4; mt++)
        relA[mt] = (uint32_t)(warp_m * 64 + mt * 16 + r + (q & 1) * 8) * 128;
    #pragma unroll
    for (int p = 0; p < 4; p++)
        relB[p] = (uint32_t)(warp_n * 64 + p * 16 + r + (q >> 1) * 8) * 128;
    const uint32_t colA = (uint32_t)(q >> 1) * 16;
    const uint32_t colB = (uint32_t)(q & 1) * 16;

    const int ntiles = K / 64;

    auto issue_stage = [&](int s) {
        const uint32_t stgA = smem_base + (uint32_t)(s % NST8) * STG8;
        const uint32_t stgB = stgA + AST8;
        const int k0 = s * 64;
        #pragma unroll
        for (int i = 0; i < 8; i++) {
            const int idx = tid + i * 128;
            const int row = idx >> 3;
            const int ch  = idx & 7;
            const uint32_t byte = (uint32_t)row * 128 + (uint32_t)ch * 16;
            cp_async_16(stgA + SW128(byte), &A[(size_t)(bm + row) * K + k0 + ch * 8]);
        }
        #pragma unroll
        for (int i = 0; i < 8; i++) {
            const int idx = tid + i * 128;
            const int row = idx >> 3;
            const int ch  = idx & 7;
            const uint32_t byte = (uint32_t)row * 128 + (uint32_t)ch * 16;
            cp_async_16(stgB + SW128(byte), &Bt[(size_t)(bn + row) * K + k0 + ch * 8]);
        }
        CP_COMMIT();
    };

    float acc[4][8][4];
    #pragma unroll
    for (int mt = 0; mt < 4; mt++)
        #pragma unroll
        for (int nt = 0; nt < 8; nt++)
            #pragma unroll
            for (int i = 0; i < 4; i++) acc[mt][nt][i] = 0.f;

    issue_stage(0);
    issue_stage(1);

    for (int it = 0; it < ntiles; it++) {
        if (it + 1 < ntiles) CP_WAIT(1); else CP_WAIT(0);
        __syncthreads();
        if (it + 2 < ntiles) issue_stage(it + 2);

        const uint32_t stgA = smem_base + (uint32_t)(it % NST8) * STG8;
        const uint32_t stgB = stgA + AST8;

        #pragma unroll
        for (int kk = 0; kk < 4; kk++) {
            const uint32_t offA = ((uint32_t)kk * 32 + colA) ^ xr;
            const uint32_t offB = ((uint32_t)kk * 32 + colB) ^ xr;
            uint32_t af[4][4], bf[8][2];
            #pragma unroll
            for (int mt = 0; mt < 4; mt++)
                ldsm4(af[mt], stgA + relA[mt] + offA);
            #pragma unroll
            for (int p = 0; p < 4; p++) {
                uint32_t bq[4];
                ldsm4(bq, stgB + relB[p] + offB);
                bf[2 * p][0]     = bq[0];
                bf[2 * p][1]     = bq[1];
                bf[2 * p + 1][0] = bq[2];
                bf[2 * p + 1][1] = bq[3];
            }
            #pragma unroll
            for (int mt = 0; mt < 4; mt++)
                #pragma unroll
                for (int nt = 0; nt < 8; nt++)
                    mma_f16(acc[mt][nt], af[mt], bf[nt]);
        }
    }

    #pragma unroll
    for (int mt = 0; mt < 4; mt++) {
        const int row0 = bm + warp_m * 64 + mt * 16 + g;
        #pragma unroll
        for (int nt = 0; nt < 8; nt++) {
            const int col = bn + warp_n * 64 + nt * 8 + 2 * l4;
            store2(acc[mt][nt][0], acc[mt][nt][1], &C[(size_t)row0 * N + col]);
            store2(acc[mt][nt][2], acc[mt][nt][3], &C[(size_t)(row0 + 8) * N + col]);
        }
    }
}

// ---------------------------------------------------------------------------
// FP16 flash attention v4 (round-10/12 validated): 4-warp CTAs (BQ=64),
// 32-key double-buffered KV tiles, 2 CTAs/SM.
// ---------------------------------------------------------------------------
#define BQA 64
#define KTA 32
#define MASKVAL -3.0e38f
#define QSTRH  152
#define Q_BYTES  (64 * QSTRH * 2)  // 19456
#define K_BYTES  8192u
#define V_BYTES  10240u
#define OFF_K0   ((uint32_t)Q_BYTES)
#define OFF_K1   (OFF_K0 + K_BYTES)
#define OFF_V0   (OFF_K1 + K_BYTES)
#define OFF_V1   (OFF_V0 + V_BYTES)
#define ATT_SMEM (OFF_V1 + V_BYTES)   // 56320

__global__ void __launch_bounds__(128, 2) attn_f16_v4(
    const __half* __restrict__ q16, const __half* __restrict__ k16,
    const __half* __restrict__ vT, __half* __restrict__ out)
{
    extern __shared__ uint32_t smem[];
    uint32_t smb;
    asm("{ .reg .u64 t; cvta.to.shared.u64 t, %1; cvt.u32.u64 %0, t; }"
        : "=r"(smb) : "l"(smem));
    __half* Qsh = (__half*)smem;

    const int tid  = threadIdx.x;
    const int warp = tid >> 5;
    const int lane = tid & 31;
    const int g    = lane >> 2;
    const int l4   = lane & 3;
    const int r    = lane & 7;
    const int qq   = lane >> 3;
    const int b    = blockIdx.z;
    const int h    = blockIdx.y;
    const int q0   = blockIdx.x * BQA;
    const int gkv  = h >> 2;

    // ---- Q staging ----
    for (int idx = tid; idx < 64 * 16; idx += 128) {
        const int rr = idx >> 4, c8 = idx & 15;
        *(uint4*)&Qsh[rr * QSTRH + c8 * 8] =
            *(const uint4*)&q16[(size_t)(b * SS + q0 + rr) * (HH * DD) + h * DD + c8 * 8];
    }
    __syncthreads();
    uint32_t qf[8][4];
    {
        const int lr = warp * 16;
        #pragma unroll
        for (int kk = 0; kk < 8; kk++) {
            qf[kk][0] = *(const uint32_t*)&Qsh[(lr + g)     * QSTRH + kk * 16 + 2 * l4];
            qf[kk][1] = *(const uint32_t*)&Qsh[(lr + g + 8) * QSTRH + kk * 16 + 2 * l4];
            qf[kk][2] = *(const uint32_t*)&Qsh[(lr + g)     * QSTRH + kk * 16 + 8 + 2 * l4];
            qf[kk][3] = *(const uint32_t*)&Qsh[(lr + g + 8) * QSTRH + kk * 16 + 8 + 2 * l4];
        }
    }
    __syncthreads();

    const int js    = max(0, q0 - WINW);
    const int ntile = (q0 + BQA - js) >> 5;

    const uint32_t xr = (uint32_t)r << 4;
    uint32_t relK[2];
    #pragma unroll
    for (int p = 0; p < 2; p++)
        relK[p] = (uint32_t)(p * 16 + r + (qq >> 1) * 8) * 128;
    const uint32_t colK = (uint32_t)(qq & 1) * 16;

    auto issue_tile = [&](int t) {
        const int kt0 = js + t * KTA;
        const uint32_t kb = smb + (t & 1 ? OFF_K1 : OFF_K0);
        const uint32_t vb = smb + (t & 1 ? OFF_V1 : OFF_V0);
        #pragma unroll
        for (int i = 0; i < 4; i++) {
            const int idx = tid + i * 128;
            const int key = idx >> 4, c = idx & 15;
            const uint32_t byte = (uint32_t)((c >> 3) * 32 + key) * 128 + (uint32_t)(c & 7) * 16;
            cp_async_16(kb + SW128(byte),
                &k16[((size_t)(b * SS + kt0 + key) * KVH + gkv) * DD + c * 8]);
        }
        #pragma unroll
        for (int i = 0; i < 4; i++) {
            const int idx = tid + i * 128;
            const int d = idx >> 2, cc = idx & 3;
            cp_async_16(vb + (uint32_t)(d * 80 + cc * 16),
                &vT[((size_t)(b * KVH + gkv) * DD + d) * SS + kt0 + cc * 8]);
        }
        CP_COMMIT();
    };

    float o[16][4];
    #pragma unroll
    for (int dt = 0; dt < 16; dt++)
        #pragma unroll
        for (int i = 0; i < 4; i++) o[dt][i] = 0.f;
    float m_a = -1e30f, m_b = -1e30f, l_a = 0.f, l_b = 0.f;

    const int i_lo = q0 + warp * 16;
    const int i_a  = i_lo + g;
    const int i_b  = i_a + 8;

    issue_tile(0);

    for (int t = 0; t < ntile; t++) {
        CP_WAIT(0);
        __syncthreads();
        if (t + 1 < ntile) issue_tile(t + 1);

        const int kt0 = js + t * KTA;
        const uint32_t kb = smb + (t & 1 ? OFF_K1 : OFF_K0);
        const uint32_t vb = smb + (t & 1 ? OFF_V1 : OFF_V0);

        // ---- S = Q K^T ----
        float s[4][4];
        #pragma unroll
        for (int nt = 0; nt < 4; nt++)
            #pragma unroll
            for (int i = 0; i < 4; i++) s[nt][i] = 0.f;

        #pragma unroll
        for (int kk = 0; kk < 8; kk++) {
            const uint32_t rowb = kb + (uint32_t)(kk >> 2) * (32 * 128);
            const uint32_t offK = ((uint32_t)(kk & 3) * 32 + colK) ^ xr;
            uint32_t bf[4][2];
            #pragma unroll
            for (int p = 0; p < 2; p++) {
                uint32_t bq[4];
                ldsm4(bq, rowb + relK[p] + offK);
                bf[2*p][0] = bq[0]; bf[2*p][1] = bq[1];
                bf[2*p+1][0] = bq[2]; bf[2*p+1][1] = bq[3];
            }
            #pragma unroll
            for (int nt = 0; nt < 4; nt++)
                mma_f16(s[nt], qf[kk], bf[nt]);
        }

        // ---- mask ----
        #pragma unroll
        for (int nt = 0; nt < 4; nt++) {
            const int j0 = kt0 + nt * 8;
            const bool allvalid = (j0 + 7 <= i_lo) && (i_lo + 15 - j0 < WINW);
            if (!allvalid) {
                const int ja = j0 + 2 * l4, jb = ja + 1;
                if (!(ja <= i_a && i_a - ja < WINW)) s[nt][0] = MASKVAL;
                if (!(jb <= i_a && i_a - jb < WINW)) s[nt][1] = MASKVAL;
                if (!(ja <= i_b && i_b - ja < WINW)) s[nt][2] = MASKVAL;
                if (!(jb <= i_b && i_b - jb < WINW)) s[nt][3] = MASKVAL;
            }
        }

        // ---- online softmax ----
        float ta = MASKVAL, tb = MASKVAL;
        #pragma unroll
        for (int nt = 0; nt < 4; nt++) {
            ta = fmaxf(ta, fmaxf(s[nt][0], s[nt][1]));
            tb = fmaxf(tb, fmaxf(s[nt][2], s[nt][3]));
        }
        ta = fmaxf(ta, __shfl_xor_sync(0xffffffffu, ta, 1));
        ta = fmaxf(ta, __shfl_xor_sync(0xffffffffu, ta, 2));
        tb = fmaxf(tb, __shfl_xor_sync(0xffffffffu, tb, 1));
        tb = fmaxf(tb, __shfl_xor_sync(0xffffffffu, tb, 2));

        const float mna = fmaxf(m_a, ta);
        const float mnb = fmaxf(m_b, tb);
        const float alpha_a = __expf(m_a - mna);
        const float alpha_b = __expf(m_b - mnb);
        m_a = mna; m_b = mnb;

        float ra = 0.f, rb = 0.f;
        #pragma unroll
        for (int nt = 0; nt < 4; nt++) {
            s[nt][0] = __expf(s[nt][0] - m_a);
            s[nt][1] = __expf(s[nt][1] - m_a);
            s[nt][2] = __expf(s[nt][2] - m_b);
            s[nt][3] = __expf(s[nt][3] - m_b);
            ra += s[nt][0] + s[nt][1];
            rb += s[nt][2] + s[nt][3];
        }
        ra += __shfl_xor_sync(0xffffffffu, ra, 1);
        ra += __shfl_xor_sync(0xffffffffu, ra, 2);
        rb += __shfl_xor_sync(0xffffffffu, rb, 1);
        rb += __shfl_xor_sync(0xffffffffu, rb, 2);
        l_a = l_a * alpha_a + ra;
        l_b = l_b * alpha_b + rb;

        #pragma unroll
        for (int dt = 0; dt < 16; dt++) {
            o[dt][0] *= alpha_a; o[dt][1] *= alpha_a;
            o[dt][2] *= alpha_b; o[dt][3] *= alpha_b;
        }

        // ---- O += P V ----
        #pragma unroll
        for (int kk = 0; kk < 2; kk++) {
            uint32_t ap[4];
            ap[0] = pack2h(s[2*kk][0],   s[2*kk][1]);
            ap[1] = pack2h(s[2*kk][2],   s[2*kk][3]);
            ap[2] = pack2h(s[2*kk+1][0], s[2*kk+1][1]);
            ap[3] = pack2h(s[2*kk+1][2], s[2*kk+1][3]);
            #pragma unroll
            for (int dtp = 0; dtp < 8; dtp++) {
                uint32_t addr = vb + (uint32_t)(dtp * 16 + r + (qq >> 1) * 8) * 80
                                   + (uint32_t)kk * 32 + (uint32_t)(qq & 1) * 16;
                uint32_t bq[4];
                ldsm4(bq, addr);
                uint32_t b0[2] = { bq[0], bq[1] };
                uint32_t b1[2] = { bq[2], bq[3] };
                mma_f16(o[2*dtp],     ap, b0);
                mma_f16(o[2*dtp + 1], ap, b1);
            }
        }
    }

    const float inv_a = 1.0f / l_a;
    const float inv_b = 1.0f / l_b;
    #pragma unroll
    for (int dt = 0; dt < 16; dt++) {
        const int col = h * DD + dt * 8 + 2 * l4;
        *(uint32_t*)&out[(size_t)(b * SS + i_a) * (HH * DD) + col] =
            pack2h(o[dt][0] * inv_a, o[dt][1] * inv_a);
        *(uint32_t*)&out[(size_t)(b * SS + i_b) * (HH * DD) + col] =
            pack2h(o[dt][2] * inv_b, o[dt][3] * inv_b);
    }
}

// ---------------------------------------------------------------------------
extern "C" void kernel_launch(void* const* d_in, const int* in_sizes, int n_in,
                              void* d_out, int out_size)
{
    const float* x     = (const float*)d_in[0];
    const float* w_qkv = (const float*)d_in[1];
    const float* w_o   = (const float*)d_in[2];
    float* out = (float*)d_out;

    __half* qkvh   = nullptr;
    __half* attn_h = nullptr;
    __half* xh     = nullptr;
    __half* wqkvTh = nullptr;
    __half* woTh   = nullptr;
    __half* q16p   = nullptr;
    __half* k16p   = nullptr;
    __half* vTp    = nullptr;
    cudaGetSymbolAddress((void**)&qkvh,   g_qkv_h);
    cudaGetSymbolAddress((void**)&attn_h, g_attn_h);
    cudaGetSymbolAddress((void**)&xh,     g_xh);
    cudaGetSymbolAddress((void**)&wqkvTh, g_wqkvT_h);
    cudaGetSymbolAddress((void**)&woTh,   g_woT_h);
    cudaGetSymbolAddress((void**)&q16p,   g_q16);
    cudaGetSymbolAddress((void**)&k16p,   g_k16);
    cudaGetSymbolAddress((void**)&vTp,    g_vT);

    cudaFuncSetAttribute(gemm_f16_v8<__half>,
                         cudaFuncAttributeMaxDynamicSharedMemorySize, GEMM_SMEM);
    cudaFuncSetAttribute(gemm_f16_v8<float>,
                         cudaFuncAttributeMaxDynamicSharedMemorySize, GEMM_SMEM);
    cudaFuncSetAttribute(attn_f16_v4,
                         cudaFuncAttributeMaxDynamicSharedMemorySize, ATT_SMEM);

    // 0) prep: x -> half; weights -> transposed half [N][K] (fast 64x64 tiles)
    {
        int n4 = (NROWS * EE) / 4;
        cvt_half_kernel<<<(n4 + 255) / 256, 256>>>(x, xh, n4);
        transpose_cvt_h64<<<dim3(QKVW / 64, EE / 64), 256>>>(w_qkv, wqkvTh, EE, QKVW);
        transpose_cvt_h64<<<dim3(EE / 64, EE / 64), 256>>>(w_o, woTh, EE, EE);
    }
    // 1) QKV projection (fp16 tensor, half output)
    {
        dim3 grid(QKVW / 128, NROWS / 128);
        gemm_f16_v8<__half><<<grid, 128, GEMM_SMEM>>>(xh, wqkvTh, qkvh, NROWS, QKVW, EE);
    }
    // 2) RoPE -> q16/k16; V transpose -> vT
    {
        rope_cvt_kernel<<<NROWS, 256>>>(qkvh, q16p, k16p);
        dim3 blk(32, 8);
        vtrans_kernel<<<dim3((KVH * DD) / 32, SS / 32, BB), blk>>>(qkvh, vTp);
    }
    // 3) Flash attention (fp16)
    {
        dim3 grid(SS / BQA, HH, BB);
        attn_f16_v4<<<grid, 128, ATT_SMEM>>>(q16p, k16p, vTp, attn_h);
    }
    // 4) Output projection (fp16 tensor, fp32 output)
    {
        dim3 grid(EE / 128, NROWS / 128);
        gemm_f16_v8<float><<<grid, 128, GEMM_SMEM>>>(attn_h, woTh, out, NROWS, EE, EE);
    }
}

// round 15
// speedup vs baseline: 1.0629x; 1.0629x over previous
#include <cuda_runtime.h>
#include <cuda_fp16.h>
#include <math.h>
#include <stdint.h>

// Problem constants
#define BB   2
#define SS   2048
#define EE   2048
#define HH   16
#define KVH  4
#define DD   128
#define WINW 512
#define QKVW ((HH + 2*KVH) * DD)   // 3072
#define NROWS (BB * SS)            // 4096

// Scratch (static device globals)
__device__ __half g_qkv_h[(size_t)NROWS * QKVW];        // half qkv (pre-RoPE)
__device__ __half g_attn_h[(size_t)NROWS * HH * DD];    // attn out (half)
__device__ __half g_xh[(size_t)NROWS * EE];             // x (half) [M][K]
__device__ __half g_wqkvT_h[(size_t)QKVW * EE];         // w_qkv^T (half) [N][K]
__device__ __half g_woT_h[(size_t)EE * EE];             // w_o^T (half) [N][K]
__device__ __half g_q16[(size_t)NROWS * HH * DD];       // roped+scaled Q half
__device__ __half g_k16[(size_t)NROWS * KVH * DD];      // roped K half
__device__ __half g_vT[(size_t)BB * KVH * DD * SS];     // V half, [b][kv][d][s]

__device__ __forceinline__ uint32_t pack2h(float a, float b) {
    __half2 h = __floats2half2_rn(a, b);
    return *(uint32_t*)&h;
}

__device__ __forceinline__ void mma_f16(float* c, const uint32_t* a, const uint32_t* b) {
    asm volatile(
        "mma.sync.aligned.m16n8k16.row.col.f32.f16.f16.f32 "
        "{%0,%1,%2,%3}, {%4,%5,%6,%7}, {%8,%9}, {%0,%1,%2,%3};\n"
        : "+f"(c[0]), "+f"(c[1]), "+f"(c[2]), "+f"(c[3])
        : "r"(a[0]), "r"(a[1]), "r"(a[2]), "r"(a[3]), "r"(b[0]), "r"(b[1]));
}

__device__ __forceinline__ void ldsm4(uint32_t* d, uint32_t a) {
    asm volatile("ldmatrix.sync.aligned.m8n8.x4.shared.b16 {%0,%1,%2,%3}, [%4];"
        : "=r"(d[0]), "=r"(d[1]), "=r"(d[2]), "=r"(d[3]) : "r"(a));
}

__device__ __forceinline__ void cp_async_16(uint32_t smem_addr, const void* gptr) {
    asm volatile("cp.async.cg.shared.global [%0], [%1], 16;" :: "r"(smem_addr), "l"(gptr));
}

#define CP_COMMIT()  asm volatile("cp.async.commit_group;" ::: "memory")
#define CP_WAIT(n)   asm volatile("cp.async.wait_group %0;" :: "n"(n) : "memory")

#define SW128(b) ((b) ^ ((((uint32_t)(b)) >> 3) & 0x70))

// epilogue store helpers (overload on output type)
__device__ __forceinline__ void store2(float a, float b, float* p) {
    *(float2*)p = make_float2(a, b);
}
__device__ __forceinline__ void store2(float a, float b, __half* p) {
    *(uint32_t*)p = pack2h(a, b);
}

// ---------------------------------------------------------------------------
// Prep: fp32 -> half  (R12-exact versions)
// ---------------------------------------------------------------------------
__global__ void cvt_half_kernel(const float* __restrict__ in, __half* __restrict__ outp, int n4)
{
    int i = blockIdx.x * blockDim.x + threadIdx.x;
    if (i < n4) {
        float4 v = ((const float4*)in)[i];
        uint2 u;
        u.x = pack2h(v.x, v.y);
        u.y = pack2h(v.z, v.w);
        ((uint2*)outp)[i] = u;
    }
}

// in [R][C] fp32 -> out [C][R] half (R12-exact 32x32 tiles)
__global__ void transpose_cvt_h_kernel(const float* __restrict__ in, __half* __restrict__ outp,
                                       int R, int C)
{
    __shared__ __half t[32][34];
    const int bx = blockIdx.x * 32;
    const int by = blockIdx.y * 32;
    #pragma unroll
    for (int j = 0; j < 4; j++)
        t[threadIdx.y + j * 8][threadIdx.x] =
            __float2half_rn(in[(size_t)(by + threadIdx.y + j * 8) * C + bx + threadIdx.x]);
    __syncthreads();
    #pragma unroll
    for (int j = 0; j < 4; j++)
        outp[(size_t)(bx + threadIdx.y + j * 8) * R + by + threadIdx.x] =
            t[threadIdx.x][threadIdx.y + j * 8];
}

// V transpose: g_qkv_h V slice [s][c] (per batch) -> vT[(b*512+c)][s]
__global__ void vtrans_kernel(const __half* __restrict__ qkv, __half* __restrict__ vT)
{
    __shared__ __half t[32][34];
    const int b  = blockIdx.z;
    const int bx = blockIdx.x * 32;   // c base
    const int by = blockIdx.y * 32;   // s base
    #pragma unroll
    for (int j = 0; j < 4; j++)
        t[threadIdx.y + j * 8][threadIdx.x] =
            qkv[(size_t)(b * SS + by + threadIdx.y + j * 8) * QKVW
                + (HH + KVH) * DD + bx + threadIdx.x];
    __syncthreads();
    #pragma unroll
    for (int j = 0; j < 4; j++)
        vT[(size_t)(b * (KVH * DD) + bx + threadIdx.y + j * 8) * SS + by + threadIdx.x] =
            t[threadIdx.x][threadIdx.y + j * 8];
}

// ---------------------------------------------------------------------------
// RoPE: fused rope + half convert, reads half qkv.
// ---------------------------------------------------------------------------
__global__ void __launch_bounds__(256) rope_cvt_kernel(
    const __half* __restrict__ qkv,
    __half* __restrict__ q16, __half* __restrict__ k16)
{
    __shared__ float cs[64], sn[64];
    const int bs = blockIdx.x;
    const int t  = threadIdx.x;
    const int s  = bs & (SS - 1);

    if (t < 64) {
        const float inv_freq = exp2f(-(float)t * 0.311430758895690262f);
        sincosf((float)s * inv_freq, &sn[t], &cs[t]);
    }
    __syncthreads();

    const __half* row = qkv + (size_t)bs * QKVW;
    const float scale = 0.088388347648318447f;  // 1/sqrt(128)

    for (int p = t; p < (HH + KVH) * 64; p += 256) {
        const int head = p >> 6;
        const int d    = p & 63;
        const __half* base = row + (head < HH ? head * DD : HH * DD + (head - HH) * DD);
        const float x0 = __half2float(base[d]);
        const float x1 = __half2float(base[d + 64]);
        const float r0 = x0 * cs[d] - x1 * sn[d];
        const float r1 = x1 * cs[d] + x0 * sn[d];
        if (head < HH) {
            __half* dst = q16 + (size_t)bs * (HH * DD) + head * DD;
            dst[d]      = __float2half_rn(r0 * scale);
            dst[d + 64] = __float2half_rn(r1 * scale);
        } else {
            __half* dst = k16 + (size_t)bs * (KVH * DD) + (head - HH) * DD;
            dst[d]      = __float2half_rn(r0);
            dst[d + 64] = __float2half_rn(r1);
        }
    }
}

// ---------------------------------------------------------------------------
// FP16 mma.sync GEMM v8 (round-12 validated, byte-identical): CTA 128x128,
// 4 warps (2m x 2n), warp tile 64x64, BK=64, 3-stage cp.async, 2 CTAs/SM.
// ---------------------------------------------------------------------------
#define AST8  16384u
#define STG8  32768u
#define NST8  3
#define GEMM_SMEM (NST8 * STG8)      // 98304

template <typename OutT>
__global__ void __launch_bounds__(128, 2) gemm_f16_v8(
    const __half* __restrict__ A, const __half* __restrict__ Bt,
    OutT* __restrict__ C, int M, int N, int K)
{
    extern __shared__ uint32_t smu[];
    uint32_t smem_base;
    asm("{ .reg .u64 t; cvta.to.shared.u64 t, %1; cvt.u32.u64 %0, t; }"
        : "=r"(smem_base) : "l"(smu));

    const int tid    = threadIdx.x;
    const int warp   = tid >> 5;
    const int lane   = tid & 31;
    const int g      = lane >> 2;
    const int l4     = lane & 3;
    const int r      = lane & 7;
    const int q      = lane >> 3;
    const int warp_m = warp >> 1;
    const int warp_n = warp & 1;
    const int bm     = blockIdx.y * 128;
    const int bn     = blockIdx.x * 128;

    const uint32_t xr = (uint32_t)r << 4;

    uint32_t relA[4], relB[4];
    #pragma unroll
    for (int mt = 0; mt < 4; mt++)
        relA[mt] = (uint32_t)(warp_m * 64 + mt * 16 + r + (q & 1) * 8) * 128;
    #pragma unroll
    for (int p = 0; p < 4; p++)
        relB[p] = (uint32_t)(warp_n * 64 + p * 16 + r + (q >> 1) * 8) * 128;
    const uint32_t colA = (uint32_t)(q >> 1) * 16;
    const uint32_t colB = (uint32_t)(q & 1) * 16;

    const int ntiles = K / 64;

    auto issue_stage = [&](int s) {
        const uint32_t stgA = smem_base + (uint32_t)(s % NST8) * STG8;
        const uint32_t stgB = stgA + AST8;
        const int k0 = s * 64;
        #pragma unroll
        for (int i = 0; i < 8; i++) {
            const int idx = tid + i * 128;
            const int row = idx >> 3;
            const int ch  = idx & 7;
            const uint32_t byte = (uint32_t)row * 128 + (uint32_t)ch * 16;
            cp_async_16(stgA + SW128(byte), &A[(size_t)(bm + row) * K + k0 + ch * 8]);
        }
        #pragma unroll
        for (int i = 0; i < 8; i++) {
            const int idx = tid + i * 128;
            const int row = idx >> 3;
            const int ch  = idx & 7;
            const uint32_t byte = (uint32_t)row * 128 + (uint32_t)ch * 16;
            cp_async_16(stgB + SW128(byte), &Bt[(size_t)(bn + row) * K + k0 + ch * 8]);
        }
        CP_COMMIT();
    };

    float acc[4][8][4];
    #pragma unroll
    for (int mt = 0; mt < 4; mt++)
        #pragma unroll
        for (int nt = 0; nt < 8; nt++)
            #pragma unroll
            for (int i = 0; i < 4; i++) acc[mt][nt][i] = 0.f;

    issue_stage(0);
    issue_stage(1);

    for (int it = 0; it < ntiles; it++) {
        if (it + 1 < ntiles) CP_WAIT(1); else CP_WAIT(0);
        __syncthreads();
        if (it + 2 < ntiles) issue_stage(it + 2);

        const uint32_t stgA = smem_base + (uint32_t)(it % NST8) * STG8;
        const uint32_t stgB = stgA + AST8;

        #pragma unroll
        for (int kk = 0; kk < 4; kk++) {
            const uint32_t offA = ((uint32_t)kk * 32 + colA) ^ xr;
            const uint32_t offB = ((uint32_t)kk * 32 + colB) ^ xr;
            uint32_t af[4][4], bf[8][2];
            #pragma unroll
            for (int mt = 0; mt < 4; mt++)
                ldsm4(af[mt], stgA + relA[mt] + offA);
            #pragma unroll
            for (int p = 0; p < 4; p++) {
                uint32_t bq[4];
                ldsm4(bq, stgB + relB[p] + offB);
                bf[2 * p][0]     = bq[0];
                bf[2 * p][1]     = bq[1];
                bf[2 * p + 1][0] = bq[2];
                bf[2 * p + 1][1] = bq[3];
            }
            #pragma unroll
            for (int mt = 0; mt < 4; mt++)
                #pragma unroll
                for (int nt = 0; nt < 8; nt++)
                    mma_f16(acc[mt][nt], af[mt], bf[nt]);
        }
    }

    #pragma unroll
    for (int mt = 0; mt < 4; mt++) {
        const int row0 = bm + warp_m * 64 + mt * 16 + g;
        #pragma unroll
        for (int nt = 0; nt < 8; nt++) {
            const int col = bn + warp_n * 64 + nt * 8 + 2 * l4;
            store2(acc[mt][nt][0], acc[mt][nt][1], &C[(size_t)row0 * N + col]);
            store2(acc[mt][nt][2], acc[mt][nt][3], &C[(size_t)(row0 + 8) * N + col]);
        }
    }
}

// ---------------------------------------------------------------------------
// FP16 flash attention v6: 4-warp CTAs (BQ=64), 64-key double-buffered KV
// tiles (half the per-tile softmax/barrier overhead of v4), 2 CTAs/SM.
// K: 2 stacked 64x128B SW128 blocks. V: 128 d-rows x 144B (128B data + pad).
// ---------------------------------------------------------------------------
#define BQA 64
#define KTA 64
#define MASKVAL -3.0e38f
#define QSTRH  152
#define Q_BYTES  (64 * QSTRH * 2)  // 19456
#define K_BYTES  16384u            // 2 blocks x 64 keys x 128B
#define V_BYTES  18432u            // 128 d rows x 144B
#define OFF_K0   ((uint32_t)Q_BYTES)
#define OFF_K1   (OFF_K0 + K_BYTES)
#define OFF_V0   (OFF_K1 + K_BYTES)
#define OFF_V1   (OFF_V0 + V_BYTES)
#define ATT_SMEM (OFF_V1 + V_BYTES)   // 89088

__global__ void __launch_bounds__(128, 2) attn_f16_v6(
    const __half* __restrict__ q16, const __half* __restrict__ k16,
    const __half* __restrict__ vT, __half* __restrict__ out)
{
    extern __shared__ uint32_t smem[];
    uint32_t smb;
    asm("{ .reg .u64 t; cvta.to.shared.u64 t, %1; cvt.u32.u64 %0, t; }"
        : "=r"(smb) : "l"(smem));
    __half* Qsh = (__half*)smem;

    const int tid  = threadIdx.x;
    const int warp = tid >> 5;
    const int lane = tid & 31;
    const int g    = lane >> 2;
    const int l4   = lane & 3;
    const int r    = lane & 7;
    const int qq   = lane >> 3;
    const int b    = blockIdx.z;
    const int h    = blockIdx.y;
    const int q0   = blockIdx.x * BQA;
    const int gkv  = h >> 2;

    // ---- Q staging ----
    for (int idx = tid; idx < 64 * 16; idx += 128) {
        const int rr = idx >> 4, c8 = idx & 15;
        *(uint4*)&Qsh[rr * QSTRH + c8 * 8] =
            *(const uint4*)&q16[(size_t)(b * SS + q0 + rr) * (HH * DD) + h * DD + c8 * 8];
    }
    __syncthreads();
    uint32_t qf[8][4];
    {
        const int lr = warp * 16;
        #pragma unroll
        for (int kk = 0; kk < 8; kk++) {
            qf[kk][0] = *(const uint32_t*)&Qsh[(lr + g)     * QSTRH + kk * 16 + 2 * l4];
            qf[kk][1] = *(const uint32_t*)&Qsh[(lr + g + 8) * QSTRH + kk * 16 + 2 * l4];
            qf[kk][2] = *(const uint32_t*)&Qsh[(lr + g)     * QSTRH + kk * 16 + 8 + 2 * l4];
            qf[kk][3] = *(const uint32_t*)&Qsh[(lr + g + 8) * QSTRH + kk * 16 + 8 + 2 * l4];
        }
    }
    __syncthreads();

    const int js    = max(0, q0 - WINW);           // multiple of 64
    const int ntile = (q0 + BQA - js) >> 6;        // tiles of 64 keys

    const uint32_t xr = (uint32_t)r << 4;
    uint32_t relK[4];
    #pragma unroll
    for (int p = 0; p < 4; p++)
        relK[p] = (uint32_t)(p * 16 + r + (qq >> 1) * 8) * 128;
    const uint32_t colK = (uint32_t)(qq & 1) * 16;

    auto issue_tile = [&](int t) {
        const int kt0 = js + t * KTA;
        const uint32_t kb = smb + (t & 1 ? OFF_K1 : OFF_K0);
        const uint32_t vb = smb + (t & 1 ? OFF_V1 : OFF_V0);
        // K: 64 keys x 256B -> 2 stacked 64x128B blocks; 1024 chunks, 8/thread
        #pragma unroll
        for (int i = 0; i < 8; i++) {
            const int idx = tid + i * 128;
            const int key = idx >> 4, c = idx & 15;
            const uint32_t byte = (uint32_t)((c >> 3) * 64 + key) * 128 + (uint32_t)(c & 7) * 16;
            cp_async_16(kb + SW128(byte),
                &k16[((size_t)(b * SS + kt0 + key) * KVH + gkv) * DD + c * 8]);
        }
        // V: 128 d rows x 64 keys (128B data), row stride 144B; 1024 chunks
        #pragma unroll
        for (int i = 0; i < 8; i++) {
            const int idx = tid + i * 128;
            const int d = idx >> 3, cc = idx & 7;
            cp_async_16(vb + (uint32_t)(d * 144 + cc * 16),
                &vT[((size_t)(b * KVH + gkv) * DD + d) * SS + kt0 + cc * 8]);
        }
        CP_COMMIT();
    };

    float o[16][4];
    #pragma unroll
    for (int dt = 0; dt < 16; dt++)
        #pragma unroll
        for (int i = 0; i < 4; i++) o[dt][i] = 0.f;
    float m_a = -1e30f, m_b = -1e30f, l_a = 0.f, l_b = 0.f;

    const int i_lo = q0 + warp * 16;
    const int i_a  = i_lo + g;
    const int i_b  = i_a + 8;

    issue_tile(0);

    for (int t = 0; t < ntile; t++) {
        CP_WAIT(0);
        __syncthreads();
        if (t + 1 < ntile) issue_tile(t + 1);

        const int kt0 = js + t * KTA;
        const uint32_t kb = smb + (t & 1 ? OFF_K1 : OFF_K0);
        const uint32_t vb = smb + (t & 1 ? OFF_V1 : OFF_V0);

        // ---- S = Q K^T : 8 k16 steps over d, 8 key-octets ----
        float s[8][4];
        #pragma unroll
        for (int nt = 0; nt < 8; nt++)
            #pragma unroll
            for (int i = 0; i < 4; i++) s[nt][i] = 0.f;

        #pragma unroll
        for (int kk = 0; kk < 8; kk++) {
            const uint32_t rowb = kb + (uint32_t)(kk >> 2) * (64 * 128);
            const uint32_t offK = ((uint32_t)(kk & 3) * 32 + colK) ^ xr;
            uint32_t bf[8][2];
            #pragma unroll
            for (int p = 0; p < 4; p++) {
                uint32_t bq[4];
                ldsm4(bq, rowb + relK[p] + offK);
                bf[2*p][0] = bq[0]; bf[2*p][1] = bq[1];
                bf[2*p+1][0] = bq[2]; bf[2*p+1][1] = bq[3];
            }
            #pragma unroll
            for (int nt = 0; nt < 8; nt++)
                mma_f16(s[nt], qf[kk], bf[nt]);
        }

        // ---- mask ----
        #pragma unroll
        for (int nt = 0; nt < 8; nt++) {
            const int j0 = kt0 + nt * 8;
            const bool allvalid = (j0 + 7 <= i_lo) && (i_lo + 15 - j0 < WINW);
            if (!allvalid) {
                const int ja = j0 + 2 * l4, jb = ja + 1;
                if (!(ja <= i_a && i_a - ja < WINW)) s[nt][0] = MASKVAL;
                if (!(jb <= i_a && i_a - jb < WINW)) s[nt][1] = MASKVAL;
                if (!(ja <= i_b && i_b - ja < WINW)) s[nt][2] = MASKVAL;
                if (!(jb <= i_b && i_b - jb < WINW)) s[nt][3] = MASKVAL;
            }
        }

        // ---- online softmax ----
        float ta = MASKVAL, tb = MASKVAL;
        #pragma unroll
        for (int nt = 0; nt < 8; nt++) {
            ta = fmaxf(ta, fmaxf(s[nt][0], s[nt][1]));
            tb = fmaxf(tb, fmaxf(s[nt][2], s[nt][3]));
        }
        ta = fmaxf(ta, __shfl_xor_sync(0xffffffffu, ta, 1));
        ta = fmaxf(ta, __shfl_xor_sync(0xffffffffu, ta, 2));
        tb = fmaxf(tb, __shfl_xor_sync(0xffffffffu, tb, 1));
        tb = fmaxf(tb, __shfl_xor_sync(0xffffffffu, tb, 2));

        const float mna = fmaxf(m_a, ta);
        const float mnb = fmaxf(m_b, tb);
        const float alpha_a = __expf(m_a - mna);
        const float alpha_b = __expf(m_b - mnb);
        m_a = mna; m_b = mnb;

        float ra = 0.f, rb = 0.f;
        #pragma unroll
        for (int nt = 0; nt < 8; nt++) {
            s[nt][0] = __expf(s[nt][0] - m_a);
            s[nt][1] = __expf(s[nt][1] - m_a);
            s[nt][2] = __expf(s[nt][2] - m_b);
            s[nt][3] = __expf(s[nt][3] - m_b);
            ra += s[nt][0] + s[nt][1];
            rb += s[nt][2] + s[nt][3];
        }
        ra += __shfl_xor_sync(0xffffffffu, ra, 1);
        ra += __shfl_xor_sync(0xffffffffu, ra, 2);
        rb += __shfl_xor_sync(0xffffffffu, rb, 1);
        rb += __shfl_xor_sync(0xffffffffu, rb, 2);
        l_a = l_a * alpha_a + ra;
        l_b = l_b * alpha_b + rb;

        #pragma unroll
        for (int dt = 0; dt < 16; dt++) {
            o[dt][0] *= alpha_a; o[dt][1] *= alpha_a;
            o[dt][2] *= alpha_b; o[dt][3] *= alpha_b;
        }

        // ---- O += P V : 4 k16 steps over 64 keys ----
        #pragma unroll
        for (int kk = 0; kk < 4; kk++) {
            uint32_t ap[4];
            ap[0] = pack2h(s[2*kk][0],   s[2*kk][1]);
            ap[1] = pack2h(s[2*kk][2],   s[2*kk][3]);
            ap[2] = pack2h(s[2*kk+1][0], s[2*kk+1][1]);
            ap[3] = pack2h(s[2*kk+1][2], s[2*kk+1][3]);
            #pragma unroll
            for (int dtp = 0; dtp < 8; dtp++) {
                uint32_t addr = vb + (uint32_t)(dtp * 16 + r + (qq >> 1) * 8) * 144
                                   + (uint32_t)kk * 32 + (uint32_t)(qq & 1) * 16;
                uint32_t bq[4];
                ldsm4(bq, addr);
                uint32_t b0[2] = { bq[0], bq[1] };
                uint32_t b1[2] = { bq[2], bq[3] };
                mma_f16(o[2*dtp],     ap, b0);
                mma_f16(o[2*dtp + 1], ap, b1);
            }
        }
    }

    const float inv_a = 1.0f / l_a;
    const float inv_b = 1.0f / l_b;
    #pragma unroll
    for (int dt = 0; dt < 16; dt++) {
        const int col = h * DD + dt * 8 + 2 * l4;
        *(uint32_t*)&out[(size_t)(b * SS + i_a) * (HH * DD) + col] =
            pack2h(o[dt][0] * inv_a, o[dt][1] * inv_a);
        *(uint32_t*)&out[(size_t)(b * SS + i_b) * (HH * DD) + col] =
            pack2h(o[dt][2] * inv_b, o[dt][3] * inv_b);
    }
}

// ---------------------------------------------------------------------------
extern "C" void kernel_launch(void* const* d_in, const int* in_sizes, int n_in,
                              void* d_out, int out_size)
{
    const float* x     = (const float*)d_in[0];
    const float* w_qkv = (const float*)d_in[1];
    const float* w_o   = (const float*)d_in[2];
    float* out = (float*)d_out;

    __half* qkvh   = nullptr;
    __half* attn_h = nullptr;
    __half* xh     = nullptr;
    __half* wqkvTh = nullptr;
    __half* woTh   = nullptr;
    __half* q16p   = nullptr;
    __half* k16p   = nullptr;
    __half* vTp    = nullptr;
    cudaGetSymbolAddress((void**)&qkvh,   g_qkv_h);
    cudaGetSymbolAddress((void**)&attn_h, g_attn_h);
    cudaGetSymbolAddress((void**)&xh,     g_xh);
    cudaGetSymbolAddress((void**)&wqkvTh, g_wqkvT_h);
    cudaGetSymbolAddress((void**)&woTh,   g_woT_h);
    cudaGetSymbolAddress((void**)&q16p,   g_q16);
    cudaGetSymbolAddress((void**)&k16p,   g_k16);
    cudaGetSymbolAddress((void**)&vTp,    g_vT);

    cudaFuncSetAttribute(gemm_f16_v8<__half>,
                         cudaFuncAttributeMaxDynamicSharedMemorySize, GEMM_SMEM);
    cudaFuncSetAttribute(gemm_f16_v8<float>,
                         cudaFuncAttributeMaxDynamicSharedMemorySize, GEMM_SMEM);
    cudaFuncSetAttribute(attn_f16_v6,
                         cudaFuncAttributeMaxDynamicSharedMemorySize, ATT_SMEM);

    // 0) prep: x -> half; weights -> transposed half [N][K] (R12 32x32 tiles)
    {
        int n4 = (NROWS * EE) / 4;
        cvt_half_kernel<<<(n4 + 255) / 256, 256>>>(x, xh, n4);
        dim3 blk(32, 8);
        transpose_cvt_h_kernel<<<dim3(QKVW / 32, EE / 32), blk>>>(w_qkv, wqkvTh, EE, QKVW);
        transpose_cvt_h_kernel<<<dim3(EE / 32, EE / 32), blk>>>(w_o, woTh, EE, EE);
    }
    // 1) QKV projection (fp16 tensor, half output)
    {
        dim3 grid(QKVW / 128, NROWS / 128);
        gemm_f16_v8<__half><<<grid, 128, GEMM_SMEM>>>(xh, wqkvTh, qkvh, NROWS, QKVW, EE);
    }
    // 2) RoPE -> q16/k16; V transpose -> vT
    {
        rope_cvt_kernel<<<NROWS, 256>>>(qkvh, q16p, k16p);
        dim3 blk(32, 8);
        vtrans_kernel<<<dim3((KVH * DD) / 32, SS / 32, BB), blk>>>(qkvh, vTp);
    }
    // 3) Flash attention (fp16, 64-key tiles)
    {
        dim3 grid(SS / BQA, HH, BB);
        attn_f16_v6<<<grid, 128, ATT_SMEM>>>(q16p, k16p, vTp, attn_h);
    }
    // 4) Output projection (fp16 tensor, fp32 output)
    {
        dim3 grid(EE / 128, NROWS / 128);
        gemm_f16_v8<float><<<grid, 128, GEMM_SMEM>>>(attn_h, woTh, out, NROWS, EE, EE);
    }
}

// round 16
// speedup vs baseline: 1.0840x; 1.0199x over previous
#include <cuda_runtime.h>
#include <cuda_fp16.h>
#include <math.h>
#include <stdint.h>

// Problem constants
#define BB   2
#define SS   2048
#define EE   2048
#define HH   16
#define KVH  4
#define DD   128
#define WINW 512
#define QKVW ((HH + 2*KVH) * DD)   // 3072
#define NROWS (BB * SS)            // 4096

// Scratch (static device globals)
__device__ __half g_qkv_h[(size_t)NROWS * QKVW];        // half qkv (pre-RoPE)
__device__ __half g_attn_h[(size_t)NROWS * HH * DD];    // attn out (half)
__device__ __half g_xh[(size_t)NROWS * EE];             // x (half) [M][K]
__device__ __half g_wqkvT_h[(size_t)QKVW * EE];         // w_qkv^T (half) [N][K]
__device__ __half g_woT_h[(size_t)EE * EE];             // w_o^T (half) [N][K]
__device__ __half g_q16[(size_t)NROWS * HH * DD];       // roped+scaled Q half
__device__ __half g_k16[(size_t)NROWS * KVH * DD];      // roped K half
__device__ __half g_vT[(size_t)BB * KVH * DD * SS];     // V half, [b][kv][d][s]

__device__ __forceinline__ uint32_t pack2h(float a, float b) {
    __half2 h = __floats2half2_rn(a, b);
    return *(uint32_t*)&h;
}

__device__ __forceinline__ void mma_f16(float* c, const uint32_t* a, const uint32_t* b) {
    asm volatile(
        "mma.sync.aligned.m16n8k16.row.col.f32.f16.f16.f32 "
        "{%0,%1,%2,%3}, {%4,%5,%6,%7}, {%8,%9}, {%0,%1,%2,%3};\n"
        : "+f"(c[0]), "+f"(c[1]), "+f"(c[2]), "+f"(c[3])
        : "r"(a[0]), "r"(a[1]), "r"(a[2]), "r"(a[3]), "r"(b[0]), "r"(b[1]));
}

__device__ __forceinline__ void ldsm4(uint32_t* d, uint32_t a) {
    asm volatile("ldmatrix.sync.aligned.m8n8.x4.shared.b16 {%0,%1,%2,%3}, [%4];"
        : "=r"(d[0]), "=r"(d[1]), "=r"(d[2]), "=r"(d[3]) : "r"(a));
}

__device__ __forceinline__ void cp_async_16(uint32_t smem_addr, const void* gptr) {
    asm volatile("cp.async.cg.shared.global [%0], [%1], 16;" :: "r"(smem_addr), "l"(gptr));
}

#define CP_COMMIT()  asm volatile("cp.async.commit_group;" ::: "memory")
#define CP_WAIT(n)   asm volatile("cp.async.wait_group %0;" :: "n"(n) : "memory")

#define SW128(b) ((b) ^ ((((uint32_t)(b)) >> 3) & 0x70))

// epilogue store helpers (overload on output type)
__device__ __forceinline__ void store2(float a, float b, float* p) {
    *(float2*)p = make_float2(a, b);
}
__device__ __forceinline__ void store2(float a, float b, __half* p) {
    *(uint32_t*)p = pack2h(a, b);
}

// ---------------------------------------------------------------------------
// prep_all: one grid covering x->half convert + both weight transposes.
//   blocks [0, 8192)              : x cvt (quad i = bid*256 + tid)
//   blocks [8192, 8192+6144)      : w_qkv transpose tile (R=EE, C=QKVW)
//   blocks [14336, 14336+4096)    : w_o transpose tile (R=EE, C=EE)
// Bodies identical to the validated R12 kernels (1D-threaded).
// ---------------------------------------------------------------------------
#define PREP_CVT_BLKS  8192
#define PREP_WQ_BLKS   ((QKVW / 32) * (EE / 32))   // 6144
#define PREP_WO_BLKS   ((EE / 32) * (EE / 32))     // 4096
#define PREP_TOTAL     (PREP_CVT_BLKS + PREP_WQ_BLKS + PREP_WO_BLKS)

__global__ void __launch_bounds__(256) prep_all(
    const float* __restrict__ x,     __half* __restrict__ xh,
    const float* __restrict__ wqkv,  __half* __restrict__ wqkvT,
    const float* __restrict__ wo,    __half* __restrict__ woT)
{
    __shared__ __half t[32][34];
    const int bid = blockIdx.x;
    const int tx  = threadIdx.x & 31;
    const int ty  = threadIdx.x >> 5;    // 0..7

    if (bid < PREP_CVT_BLKS) {
        const int i = bid * 256 + threadIdx.x;   // quad index < 2097152
        float4 v = ((const float4*)x)[i];
        uint2 u;
        u.x = pack2h(v.x, v.y);
        u.y = pack2h(v.z, v.w);
        ((uint2*)xh)[i] = u;
        return;
    }

    const float* in;
    __half* outp;
    int R, C, bx, by;
    if (bid < PREP_CVT_BLKS + PREP_WQ_BLKS) {
        const int ti = bid - PREP_CVT_BLKS;
        in = wqkv; outp = wqkvT; R = EE; C = QKVW;
        bx = (ti % (QKVW / 32)) * 32;
        by = (ti / (QKVW / 32)) * 32;
    } else {
        const int ti = bid - PREP_CVT_BLKS - PREP_WQ_BLKS;
        in = wo; outp = woT; R = EE; C = EE;
        bx = (ti % (EE / 32)) * 32;
        by = (ti / (EE / 32)) * 32;
    }
    #pragma unroll
    for (int j = 0; j < 4; j++)
        t[ty + j * 8][tx] =
            __float2half_rn(in[(size_t)(by + ty + j * 8) * C + bx + tx]);
    __syncthreads();
    #pragma unroll
    for (int j = 0; j < 4; j++)
        outp[(size_t)(bx + ty + j * 8) * R + by + tx] = t[tx][ty + j * 8];
}

// ---------------------------------------------------------------------------
// postproc: one grid covering rope (q,k) + V transpose.
//   blocks [0, 4096)        : rope row bs = bid
//   blocks [4096, 4096+2048): vtrans 32x32 tile
// ---------------------------------------------------------------------------
#define POST_ROPE_BLKS 4096
#define POST_VT_BLKS   (BB * ((KVH * DD) / 32) * (SS / 32))   // 2048
#define POST_TOTAL     (POST_ROPE_BLKS + POST_VT_BLKS)

__global__ void __launch_bounds__(256) postproc(
    const __half* __restrict__ qkv,
    __half* __restrict__ q16, __half* __restrict__ k16, __half* __restrict__ vT)
{
    __shared__ float cs[64], sn[64];
    __shared__ __half tt[32][34];
    const int bid = blockIdx.x;

    if (bid < POST_ROPE_BLKS) {
        const int bs = bid;
        const int t  = threadIdx.x;
        const int s  = bs & (SS - 1);

        if (t < 64) {
            const float inv_freq = exp2f(-(float)t * 0.311430758895690262f);
            sincosf((float)s * inv_freq, &sn[t], &cs[t]);
        }
        __syncthreads();

        const __half* row = qkv + (size_t)bs * QKVW;
        const float scale = 0.088388347648318447f;  // 1/sqrt(128)

        for (int p = t; p < (HH + KVH) * 64; p += 256) {
            const int head = p >> 6;
            const int d    = p & 63;
            const __half* base = row + (head < HH ? head * DD : HH * DD + (head - HH) * DD);
            const float x0 = __half2float(base[d]);
            const float x1 = __half2float(base[d + 64]);
            const float r0 = x0 * cs[d] - x1 * sn[d];
            const float r1 = x1 * cs[d] + x0 * sn[d];
            if (head < HH) {
                __half* dst = q16 + (size_t)bs * (HH * DD) + head * DD;
                dst[d]      = __float2half_rn(r0 * scale);
                dst[d + 64] = __float2half_rn(r1 * scale);
            } else {
                __half* dst = k16 + (size_t)bs * (KVH * DD) + (head - HH) * DD;
                dst[d]      = __float2half_rn(r0);
                dst[d + 64] = __float2half_rn(r1);
            }
        }
        return;
    }

    // vtrans tile
    const int ti = bid - POST_ROPE_BLKS;          // 0..2047
    const int b  = ti >> 10;                      // 1024 tiles per batch
    const int tr = ti & 1023;
    const int bx = (tr & 15) * 32;                // c base (512/32 = 16)
    const int by = (tr >> 4) * 32;                // s base (2048/32 = 64)
    const int tx = threadIdx.x & 31;
    const int ty = threadIdx.x >> 5;

    #pragma unroll
    for (int j = 0; j < 4; j++)
        tt[ty + j * 8][tx] =
            qkv[(size_t)(b * SS + by + ty + j * 8) * QKVW
                + (HH + KVH) * DD + bx + tx];
    __syncthreads();
    #pragma unroll
    for (int j = 0; j < 4; j++)
        vT[(size_t)(b * (KVH * DD) + bx + ty + j * 8) * SS + by + tx] =
            tt[tx][ty + j * 8];
}

// ---------------------------------------------------------------------------
// FP16 mma.sync GEMM v8 (round-12 validated, byte-identical): CTA 128x128,
// 4 warps (2m x 2n), warp tile 64x64, BK=64, 3-stage cp.async, 2 CTAs/SM.
// ---------------------------------------------------------------------------
#define AST8  16384u
#define STG8  32768u
#define NST8  3
#define GEMM_SMEM (NST8 * STG8)      // 98304

template <typename OutT>
__global__ void __launch_bounds__(128, 2) gemm_f16_v8(
    const __half* __restrict__ A, const __half* __restrict__ Bt,
    OutT* __restrict__ C, int M, int N, int K)
{
    extern __shared__ uint32_t smu[];
    uint32_t smem_base;
    asm("{ .reg .u64 t; cvta.to.shared.u64 t, %1; cvt.u32.u64 %0, t; }"
        : "=r"(smem_base) : "l"(smu));

    const int tid    = threadIdx.x;
    const int warp   = tid >> 5;
    const int lane   = tid & 31;
    const int g      = lane >> 2;
    const int l4     = lane & 3;
    const int r      = lane & 7;
    const int q      = lane >> 3;
    const int warp_m = warp >> 1;
    const int warp_n = warp & 1;
    const int bm     = blockIdx.y * 128;
    const int bn     = blockIdx.x * 128;

    const uint32_t xr = (uint32_t)r << 4;

    uint32_t relA[4], relB[4];
    #pragma unroll
    for (int mt = 0; mt < 4; mt++)
        relA[mt] = (uint32_t)(warp_m * 64 + mt * 16 + r + (q & 1) * 8) * 128;
    #pragma unroll
    for (int p = 0; p < 4; p++)
        relB[p] = (uint32_t)(warp_n * 64 + p * 16 + r + (q >> 1) * 8) * 128;
    const uint32_t colA = (uint32_t)(q >> 1) * 16;
    const uint32_t colB = (uint32_t)(q & 1) * 16;

    const int ntiles = K / 64;

    auto issue_stage = [&](int s) {
        const uint32_t stgA = smem_base + (uint32_t)(s % NST8) * STG8;
        const uint32_t stgB = stgA + AST8;
        const int k0 = s * 64;
        #pragma unroll
        for (int i = 0; i < 8; i++) {
            const int idx = tid + i * 128;
            const int row = idx >> 3;
            const int ch  = idx & 7;
            const uint32_t byte = (uint32_t)row * 128 + (uint32_t)ch * 16;
            cp_async_16(stgA + SW128(byte), &A[(size_t)(bm + row) * K + k0 + ch * 8]);
        }
        #pragma unroll
        for (int i = 0; i < 8; i++) {
            const int idx = tid + i * 128;
            const int row = idx >> 3;
            const int ch  = idx & 7;
            const uint32_t byte = (uint32_t)row * 128 + (uint32_t)ch * 16;
            cp_async_16(stgB + SW128(byte), &Bt[(size_t)(bn + row) * K + k0 + ch * 8]);
        }
        CP_COMMIT();
    };

    float acc[4][8][4];
    #pragma unroll
    for (int mt = 0; mt < 4; mt++)
        #pragma unroll
        for (int nt = 0; nt < 8; nt++)
            #pragma unroll
            for (int i = 0; i < 4; i++) acc[mt][nt][i] = 0.f;

    issue_stage(0);
    issue_stage(1);

    for (int it = 0; it < ntiles; it++) {
        if (it + 1 < ntiles) CP_WAIT(1); else CP_WAIT(0);
        __syncthreads();
        if (it + 2 < ntiles) issue_stage(it + 2);

        const uint32_t stgA = smem_base + (uint32_t)(it % NST8) * STG8;
        const uint32_t stgB = stgA + AST8;

        #pragma unroll
        for (int kk = 0; kk < 4; kk++) {
            const uint32_t offA = ((uint32_t)kk * 32 + colA) ^ xr;
            const uint32_t offB = ((uint32_t)kk * 32 + colB) ^ xr;
            uint32_t af[4][4], bf[8][2];
            #pragma unroll
            for (int mt = 0; mt < 4; mt++)
                ldsm4(af[mt], stgA + relA[mt] + offA);
            #pragma unroll
            for (int p = 0; p < 4; p++) {
                uint32_t bq[4];
                ldsm4(bq, stgB + relB[p] + offB);
                bf[2 * p][0]     = bq[0];
                bf[2 * p][1]     = bq[1];
                bf[2 * p + 1][0] = bq[2];
                bf[2 * p + 1][1] = bq[3];
            }
            #pragma unroll
            for (int mt = 0; mt < 4; mt++)
                #pragma unroll
                for (int nt = 0; nt < 8; nt++)
                    mma_f16(acc[mt][nt], af[mt], bf[nt]);
        }
    }

    #pragma unroll
    for (int mt = 0; mt < 4; mt++) {
        const int row0 = bm + warp_m * 64 + mt * 16 + g;
        #pragma unroll
        for (int nt = 0; nt < 8; nt++) {
            const int col = bn + warp_n * 64 + nt * 8 + 2 * l4;
            store2(acc[mt][nt][0], acc[mt][nt][1], &C[(size_t)row0 * N + col]);
            store2(acc[mt][nt][2], acc[mt][nt][3], &C[(size_t)(row0 + 8) * N + col]);
        }
    }
}

// ---------------------------------------------------------------------------
// FP16 flash attention v6 (round-15 validated): 4-warp CTAs (BQ=64), 64-key
// double-buffered KV tiles, 2 CTAs/SM.
// ---------------------------------------------------------------------------
#define BQA 64
#define KTA 64
#define MASKVAL -3.0e38f
#define QSTRH  152
#define Q_BYTES  (64 * QSTRH * 2)  // 19456
#define K_BYTES  16384u
#define V_BYTES  18432u
#define OFF_K0   ((uint32_t)Q_BYTES)
#define OFF_K1   (OFF_K0 + K_BYTES)
#define OFF_V0   (OFF_K1 + K_BYTES)
#define OFF_V1   (OFF_V0 + V_BYTES)
#define ATT_SMEM (OFF_V1 + V_BYTES)   // 89088

__global__ void __launch_bounds__(128, 2) attn_f16_v6(
    const __half* __restrict__ q16, const __half* __restrict__ k16,
    const __half* __restrict__ vT, __half* __restrict__ out)
{
    extern __shared__ uint32_t smem[];
    uint32_t smb;
    asm("{ .reg .u64 t; cvta.to.shared.u64 t, %1; cvt.u32.u64 %0, t; }"
        : "=r"(smb) : "l"(smem));
    __half* Qsh = (__half*)smem;

    const int tid  = threadIdx.x;
    const int warp = tid >> 5;
    const int lane = tid & 31;
    const int g    = lane >> 2;
    const int l4   = lane & 3;
    const int r    = lane & 7;
    const int qq   = lane >> 3;
    const int b    = blockIdx.z;
    const int h    = blockIdx.y;
    const int q0   = blockIdx.x * BQA;
    const int gkv  = h >> 2;

    for (int idx = tid; idx < 64 * 16; idx += 128) {
        const int rr = idx >> 4, c8 = idx & 15;
        *(uint4*)&Qsh[rr * QSTRH + c8 * 8] =
            *(const uint4*)&q16[(size_t)(b * SS + q0 + rr) * (HH * DD) + h * DD + c8 * 8];
    }
    __syncthreads();
    uint32_t qf[8][4];
    {
        const int lr = warp * 16;
        #pragma unroll
        for (int kk = 0; kk < 8; kk++) {
            qf[kk][0] = *(const uint32_t*)&Qsh[(lr + g)     * QSTRH + kk * 16 + 2 * l4];
            qf[kk][1] = *(const uint32_t*)&Qsh[(lr + g + 8) * QSTRH + kk * 16 + 2 * l4];
            qf[kk][2] = *(const uint32_t*)&Qsh[(lr + g)     * QSTRH + kk * 16 + 8 + 2 * l4];
            qf[kk][3] = *(const uint32_t*)&Qsh[(lr + g + 8) * QSTRH + kk * 16 + 8 + 2 * l4];
        }
    }
    __syncthreads();

    const int js    = max(0, q0 - WINW);
    const int ntile = (q0 + BQA - js) >> 6;

    const uint32_t xr = (uint32_t)r << 4;
    uint32_t relK[4];
    #pragma unroll
    for (int p = 0; p < 4; p++)
        relK[p] = (uint32_t)(p * 16 + r + (qq >> 1) * 8) * 128;
    const uint32_t colK = (uint32_t)(qq & 1) * 16;

    auto issue_tile = [&](int t) {
        const int kt0 = js + t * KTA;
        const uint32_t kb = smb + (t & 1 ? OFF_K1 : OFF_K0);
        const uint32_t vb = smb + (t & 1 ? OFF_V1 : OFF_V0);
        #pragma unroll
        for (int i = 0; i < 8; i++) {
            const int idx = tid + i * 128;
            const int key = idx >> 4, c = idx & 15;
            const uint32_t byte = (uint32_t)((c >> 3) * 64 + key) * 128 + (uint32_t)(c & 7) * 16;
            cp_async_16(kb + SW128(byte),
                &k16[((size_t)(b * SS + kt0 + key) * KVH + gkv) * DD + c * 8]);
        }
        #pragma unroll
        for (int i = 0; i < 8; i++) {
            const int idx = tid + i * 128;
            const int d = idx >> 3, cc = idx & 7;
            cp_async_16(vb + (uint32_t)(d * 144 + cc * 16),
                &vT[((size_t)(b * KVH + gkv) * DD + d) * SS + kt0 + cc * 8]);
        }
        CP_COMMIT();
    };

    float o[16][4];
    #pragma unroll
    for (int dt = 0; dt < 16; dt++)
        #pragma unroll
        for (int i = 0; i < 4; i++) o[dt][i] = 0.f;
    float m_a = -1e30f, m_b = -1e30f, l_a = 0.f, l_b = 0.f;

    const int i_lo = q0 + warp * 16;
    const int i_a  = i_lo + g;
    const int i_b  = i_a + 8;

    issue_tile(0);

    for (int t = 0; t < ntile; t++) {
        CP_WAIT(0);
        __syncthreads();
        if (t + 1 < ntile) issue_tile(t + 1);

        const int kt0 = js + t * KTA;
        const uint32_t kb = smb + (t & 1 ? OFF_K1 : OFF_K0);
        const uint32_t vb = smb + (t & 1 ? OFF_V1 : OFF_V0);

        float s[8][4];
        #pragma unroll
        for (int nt = 0; nt < 8; nt++)
            #pragma unroll
            for (int i = 0; i < 4; i++) s[nt][i] = 0.f;

        #pragma unroll
        for (int kk = 0; kk < 8; kk++) {
            const uint32_t rowb = kb + (uint32_t)(kk >> 2) * (64 * 128);
            const uint32_t offK = ((uint32_t)(kk & 3) * 32 + colK) ^ xr;
            uint32_t bf[8][2];
            #pragma unroll
            for (int p = 0; p < 4; p++) {
                uint32_t bq[4];
                ldsm4(bq, rowb + relK[p] + offK);
                bf[2*p][0] = bq[0]; bf[2*p][1] = bq[1];
                bf[2*p+1][0] = bq[2]; bf[2*p+1][1] = bq[3];
            }
            #pragma unroll
            for (int nt = 0; nt < 8; nt++)
                mma_f16(s[nt], qf[kk], bf[nt]);
        }

        #pragma unroll
        for (int nt = 0; nt < 8; nt++) {
            const int j0 = kt0 + nt * 8;
            const bool allvalid = (j0 + 7 <= i_lo) && (i_lo + 15 - j0 < WINW);
            if (!allvalid) {
                const int ja = j0 + 2 * l4, jb = ja + 1;
                if (!(ja <= i_a && i_a - ja < WINW)) s[nt][0] = MASKVAL;
                if (!(jb <= i_a && i_a - jb < WINW)) s[nt][1] = MASKVAL;
                if (!(ja <= i_b && i_b - ja < WINW)) s[nt][2] = MASKVAL;
                if (!(jb <= i_b && i_b - jb < WINW)) s[nt][3] = MASKVAL;
            }
        }

        float ta = MASKVAL, tb = MASKVAL;
        #pragma unroll
        for (int nt = 0; nt < 8; nt++) {
            ta = fmaxf(ta, fmaxf(s[nt][0], s[nt][1]));
            tb = fmaxf(tb, fmaxf(s[nt][2], s[nt][3]));
        }
        ta = fmaxf(ta, __shfl_xor_sync(0xffffffffu, ta, 1));
        ta = fmaxf(ta, __shfl_xor_sync(0xffffffffu, ta, 2));
        tb = fmaxf(tb, __shfl_xor_sync(0xffffffffu, tb, 1));
        tb = fmaxf(tb, __shfl_xor_sync(0xffffffffu, tb, 2));

        const float mna = fmaxf(m_a, ta);
        const float mnb = fmaxf(m_b, tb);
        const float alpha_a = __expf(m_a - mna);
        const float alpha_b = __expf(m_b - mnb);
        m_a = mna; m_b = mnb;

        float ra = 0.f, rb = 0.f;
        #pragma unroll
        for (int nt = 0; nt < 8; nt++) {
            s[nt][0] = __expf(s[nt][0] - m_a);
            s[nt][1] = __expf(s[nt][1] - m_a);
            s[nt][2] = __expf(s[nt][2] - m_b);
            s[nt][3] = __expf(s[nt][3] - m_b);
            ra += s[nt][0] + s[nt][1];
            rb += s[nt][2] + s[nt][3];
        }
        ra += __shfl_xor_sync(0xffffffffu, ra, 1);
        ra += __shfl_xor_sync(0xffffffffu, ra, 2);
        rb += __shfl_xor_sync(0xffffffffu, rb, 1);
        rb += __shfl_xor_sync(0xffffffffu, rb, 2);
        l_a = l_a * alpha_a + ra;
        l_b = l_b * alpha_b + rb;

        #pragma unroll
        for (int dt = 0; dt < 16; dt++) {
            o[dt][0] *= alpha_a; o[dt][1] *= alpha_a;
            o[dt][2] *= alpha_b; o[dt][3] *= alpha_b;
        }

        #pragma unroll
        for (int kk = 0; kk < 4; kk++) {
            uint32_t ap[4];
            ap[0] = pack2h(s[2*kk][0],   s[2*kk][1]);
            ap[1] = pack2h(s[2*kk][2],   s[2*kk][3]);
            ap[2] = pack2h(s[2*kk+1][0], s[2*kk+1][1]);
            ap[3] = pack2h(s[2*kk+1][2], s[2*kk+1][3]);
            #pragma unroll
            for (int dtp = 0; dtp < 8; dtp++) {
                uint32_t addr = vb + (uint32_t)(dtp * 16 + r + (qq >> 1) * 8) * 144
                                   + (uint32_t)kk * 32 + (uint32_t)(qq & 1) * 16;
                uint32_t bq[4];
                ldsm4(bq, addr);
                uint32_t b0[2] = { bq[0], bq[1] };
                uint32_t b1[2] = { bq[2], bq[3] };
                mma_f16(o[2*dtp],     ap, b0);
                mma_f16(o[2*dtp + 1], ap, b1);
            }
        }
    }

    const float inv_a = 1.0f / l_a;
    const float inv_b = 1.0f / l_b;
    #pragma unroll
    for (int dt = 0; dt < 16; dt++) {
        const int col = h * DD + dt * 8 + 2 * l4;
        *(uint32_t*)&out[(size_t)(b * SS + i_a) * (HH * DD) + col] =
            pack2h(o[dt][0] * inv_a, o[dt][1] * inv_a);
        *(uint32_t*)&out[(size_t)(b * SS + i_b) * (HH * DD) + col] =
            pack2h(o[dt][2] * inv_b, o[dt][3] * inv_b);
    }
}

// ---------------------------------------------------------------------------
extern "C" void kernel_launch(void* const* d_in, const int* in_sizes, int n_in,
                              void* d_out, int out_size)
{
    const float* x     = (const float*)d_in[0];
    const float* w_qkv = (const float*)d_in[1];
    const float* w_o   = (const float*)d_in[2];
    float* out = (float*)d_out;

    __half* qkvh   = nullptr;
    __half* attn_h = nullptr;
    __half* xh     = nullptr;
    __half* wqkvTh = nullptr;
    __half* woTh   = nullptr;
    __half* q16p   = nullptr;
    __half* k16p   = nullptr;
    __half* vTp    = nullptr;
    cudaGetSymbolAddress((void**)&qkvh,   g_qkv_h);
    cudaGetSymbolAddress((void**)&attn_h, g_attn_h);
    cudaGetSymbolAddress((void**)&xh,     g_xh);
    cudaGetSymbolAddress((void**)&wqkvTh, g_wqkvT_h);
    cudaGetSymbolAddress((void**)&woTh,   g_woT_h);
    cudaGetSymbolAddress((void**)&q16p,   g_q16);
    cudaGetSymbolAddress((void**)&k16p,   g_k16);
    cudaGetSymbolAddress((void**)&vTp,    g_vT);

    cudaFuncSetAttribute(gemm_f16_v8<__half>,
                         cudaFuncAttributeMaxDynamicSharedMemorySize, GEMM_SMEM);
    cudaFuncSetAttribute(gemm_f16_v8<float>,
                         cudaFuncAttributeMaxDynamicSharedMemorySize, GEMM_SMEM);
    cudaFuncSetAttribute(attn_f16_v6,
                         cudaFuncAttributeMaxDynamicSharedMemorySize, ATT_SMEM);

    // 0) prep: single merged launch (x cvt + both weight transposes)
    prep_all<<<PREP_TOTAL, 256>>>(x, xh, w_qkv, wqkvTh, w_o, woTh);

    // 1) QKV projection (fp16 tensor, half output)
    {
        dim3 grid(QKVW / 128, NROWS / 128);
        gemm_f16_v8<__half><<<grid, 128, GEMM_SMEM>>>(xh, wqkvTh, qkvh, NROWS, QKVW, EE);
    }
    // 2) RoPE + V transpose: single merged launch
    postproc<<<POST_TOTAL, 256>>>(qkvh, q16p, k16p, vTp);

    // 3) Flash attention (fp16, 64-key tiles)
    {
        dim3 grid(SS / BQA, HH, BB);
        attn_f16_v6<<<grid, 128, ATT_SMEM>>>(q16p, k16p, vTp, attn_h);
    }
    // 4) Output projection (fp16 tensor, fp32 output)
    {
        dim3 grid(EE / 128, NROWS / 128);
        gemm_f16_v8<float><<<grid, 128, GEMM_SMEM>>>(attn_h, woTh, out, NROWS, EE, EE);
    }
}

// round 17
// speedup vs baseline: 1.1307x; 1.0431x over previous
#include <cuda_runtime.h>
#include <cuda_fp16.h>
#include <math.h>
#include <stdint.h>

// Problem constants
#define BB   2
#define SS   2048
#define EE   2048
#define HH   16
#define KVH  4
#define DD   128
#define WINW 512
#define QKVW ((HH + 2*KVH) * DD)   // 3072
#define NROWS (BB * SS)            // 4096

// Scratch (static device globals)
__device__ __half g_qkv_h[(size_t)NROWS * QKVW];
__device__ __half g_attn_h[(size_t)NROWS * HH * DD];
__device__ __half g_xh[(size_t)NROWS * EE];
__device__ __half g_wqkvT_h[(size_t)QKVW * EE];
__device__ __half g_woT_h[(size_t)EE * EE];
__device__ __half g_q16[(size_t)NROWS * HH * DD];
__device__ __half g_k16[(size_t)NROWS * KVH * DD];
__device__ __half g_vT[(size_t)BB * KVH * DD * SS];

__device__ __forceinline__ uint32_t pack2h(float a, float b) {
    __half2 h = __floats2half2_rn(a, b);
    return *(uint32_t*)&h;
}

__device__ __forceinline__ void mma_f16(float* c, const uint32_t* a, const uint32_t* b) {
    asm volatile(
        "mma.sync.aligned.m16n8k16.row.col.f32.f16.f16.f32 "
        "{%0,%1,%2,%3}, {%4,%5,%6,%7}, {%8,%9}, {%0,%1,%2,%3};\n"
        : "+f"(c[0]), "+f"(c[1]), "+f"(c[2]), "+f"(c[3])
        : "r"(a[0]), "r"(a[1]), "r"(a[2]), "r"(a[3]), "r"(b[0]), "r"(b[1]));
}

__device__ __forceinline__ void ldsm4(uint32_t* d, uint32_t a) {
    asm volatile("ldmatrix.sync.aligned.m8n8.x4.shared.b16 {%0,%1,%2,%3}, [%4];"
        : "=r"(d[0]), "=r"(d[1]), "=r"(d[2]), "=r"(d[3]) : "r"(a));
}

__device__ __forceinline__ void cp_async_16(uint32_t smem_addr, const void* gptr) {
    asm volatile("cp.async.cg.shared.global [%0], [%1], 16;" :: "r"(smem_addr), "l"(gptr));
}

#define CP_COMMIT()  asm volatile("cp.async.commit_group;" ::: "memory")
#define CP_WAIT(n)   asm volatile("cp.async.wait_group %0;" :: "n"(n) : "memory")

#define SW128(b) ((b) ^ ((((uint32_t)(b)) >> 3) & 0x70))

__device__ __forceinline__ void store2(float a, float b, float* p) {
    *(float2*)p = make_float2(a, b);
}
__device__ __forceinline__ void store2(float a, float b, __half* p) {
    *(uint32_t*)p = pack2h(a, b);
}

// ---------------------------------------------------------------------------
// prep_all (round-16 validated): x cvt + both weight transposes, one grid.
// ---------------------------------------------------------------------------
#define PREP_CVT_BLKS  8192
#define PREP_WQ_BLKS   ((QKVW / 32) * (EE / 32))
#define PREP_WO_BLKS   ((EE / 32) * (EE / 32))
#define PREP_TOTAL     (PREP_CVT_BLKS + PREP_WQ_BLKS + PREP_WO_BLKS)

__global__ void __launch_bounds__(256) prep_all(
    const float* __restrict__ x,     __half* __restrict__ xh,
    const float* __restrict__ wqkv,  __half* __restrict__ wqkvT,
    const float* __restrict__ wo,    __half* __restrict__ woT)
{
    __shared__ __half t[32][34];
    const int bid = blockIdx.x;
    const int tx  = threadIdx.x & 31;
    const int ty  = threadIdx.x >> 5;

    if (bid < PREP_CVT_BLKS) {
        const int i = bid * 256 + threadIdx.x;
        float4 v = ((const float4*)x)[i];
        uint2 u;
        u.x = pack2h(v.x, v.y);
        u.y = pack2h(v.z, v.w);
        ((uint2*)xh)[i] = u;
        return;
    }

    const float* in;
    __half* outp;
    int R, C, bx, by;
    if (bid < PREP_CVT_BLKS + PREP_WQ_BLKS) {
        const int ti = bid - PREP_CVT_BLKS;
        in = wqkv; outp = wqkvT; R = EE; C = QKVW;
        bx = (ti % (QKVW / 32)) * 32;
        by = (ti / (QKVW / 32)) * 32;
    } else {
        const int ti = bid - PREP_CVT_BLKS - PREP_WQ_BLKS;
        in = wo; outp = woT; R = EE; C = EE;
        bx = (ti % (EE / 32)) * 32;
        by = (ti / (EE / 32)) * 32;
    }
    #pragma unroll
    for (int j = 0; j < 4; j++)
        t[ty + j * 8][tx] =
            __float2half_rn(in[(size_t)(by + ty + j * 8) * C + bx + tx]);
    __syncthreads();
    #pragma unroll
    for (int j = 0; j < 4; j++)
        outp[(size_t)(bx + ty + j * 8) * R + by + tx] = t[tx][ty + j * 8];
}

// ---------------------------------------------------------------------------
// postproc (round-16 validated): rope + V transpose, one grid.
// ---------------------------------------------------------------------------
#define POST_ROPE_BLKS 4096
#define POST_VT_BLKS   (BB * ((KVH * DD) / 32) * (SS / 32))
#define POST_TOTAL     (POST_ROPE_BLKS + POST_VT_BLKS)

__global__ void __launch_bounds__(256) postproc(
    const __half* __restrict__ qkv,
    __half* __restrict__ q16, __half* __restrict__ k16, __half* __restrict__ vT)
{
    __shared__ float cs[64], sn[64];
    __shared__ __half tt[32][34];
    const int bid = blockIdx.x;

    if (bid < POST_ROPE_BLKS) {
        const int bs = bid;
        const int t  = threadIdx.x;
        const int s  = bs & (SS - 1);

        if (t < 64) {
            const float inv_freq = exp2f(-(float)t * 0.311430758895690262f);
            sincosf((float)s * inv_freq, &sn[t], &cs[t]);
        }
        __syncthreads();

        const __half* row = qkv + (size_t)bs * QKVW;
        const float scale = 0.088388347648318447f;

        for (int p = t; p < (HH + KVH) * 64; p += 256) {
            const int head = p >> 6;
            const int d    = p & 63;
            const __half* base = row + (head < HH ? head * DD : HH * DD + (head - HH) * DD);
            const float x0 = __half2float(base[d]);
            const float x1 = __half2float(base[d + 64]);
            const float r0 = x0 * cs[d] - x1 * sn[d];
            const float r1 = x1 * cs[d] + x0 * sn[d];
            if (head < HH) {
                __half* dst = q16 + (size_t)bs * (HH * DD) + head * DD;
                dst[d]      = __float2half_rn(r0 * scale);
                dst[d + 64] = __float2half_rn(r1 * scale);
            } else {
                __half* dst = k16 + (size_t)bs * (KVH * DD) + (head - HH) * DD;
                dst[d]      = __float2half_rn(r0);
                dst[d + 64] = __float2half_rn(r1);
            }
        }
        return;
    }

    const int ti = bid - POST_ROPE_BLKS;
    const int b  = ti >> 10;
    const int tr = ti & 1023;
    const int bx = (tr & 15) * 32;
    const int by = (tr >> 4) * 32;
    const int tx = threadIdx.x & 31;
    const int ty = threadIdx.x >> 5;

    #pragma unroll
    for (int j = 0; j < 4; j++)
        tt[ty + j * 8][tx] =
            qkv[(size_t)(b * SS + by + ty + j * 8) * QKVW
                + (HH + KVH) * DD + bx + tx];
    __syncthreads();
    #pragma unroll
    for (int j = 0; j < 4; j++)
        vT[(size_t)(b * (KVH * DD) + bx + ty + j * 8) * SS + by + tx] =
            tt[tx][ty + j * 8];
}

// ---------------------------------------------------------------------------
// FP16 mma.sync GEMM v10: persistent CTAs. Mainloop/addressing identical to
// the validated v8; wrapped in a tile loop (tile += gridDim.x) with per-tile
// accumulator reset + pipeline re-prime.  CTA 128x128, 4 warps, warp tile
// 64x64, BK=64, 3-stage cp.async, 2 CTAs/SM.
// ---------------------------------------------------------------------------
#define AST8  16384u
#define STG8  32768u
#define NST8  3
#define GEMM_SMEM (NST8 * STG8)
#define GEMM_PERSIST_CTAS 296

template <typename OutT>
__global__ void __launch_bounds__(128, 2) gemm_f16_v10(
    const __half* __restrict__ A, const __half* __restrict__ Bt,
    OutT* __restrict__ C, int M, int N, int K)
{
    extern __shared__ uint32_t smu[];
    uint32_t smem_base;
    asm("{ .reg .u64 t; cvta.to.shared.u64 t, %1; cvt.u32.u64 %0, t; }"
        : "=r"(smem_base) : "l"(smu));

    const int tid    = threadIdx.x;
    const int warp   = tid >> 5;
    const int lane   = tid & 31;
    const int g      = lane >> 2;
    const int l4     = lane & 3;
    const int r      = lane & 7;
    const int q      = lane >> 3;
    const int warp_m = warp >> 1;
    const int warp_n = warp & 1;

    const uint32_t xr = (uint32_t)r << 4;

    uint32_t relA[4], relB[4];
    #pragma unroll
    for (int mt = 0; mt < 4; mt++)
        relA[mt] = (uint32_t)(warp_m * 64 + mt * 16 + r + (q & 1) * 8) * 128;
    #pragma unroll
    for (int p = 0; p < 4; p++)
        relB[p] = (uint32_t)(warp_n * 64 + p * 16 + r + (q >> 1) * 8) * 128;
    const uint32_t colA = (uint32_t)(q >> 1) * 16;
    const uint32_t colB = (uint32_t)(q & 1) * 16;

    const int ntiles  = K / 64;
    const int ntn     = N >> 7;
    const int ttot    = (M >> 7) * ntn;

    for (int tile = blockIdx.x; tile < ttot; tile += gridDim.x) {
        const int bm = (tile / ntn) << 7;
        const int bn = (tile % ntn) << 7;

        // guard smem buffer reuse across tile iterations
        __syncthreads();

        auto issue_stage = [&](int s) {
            const uint32_t stgA = smem_base + (uint32_t)(s % NST8) * STG8;
            const uint32_t stgB = stgA + AST8;
            const int k0 = s * 64;
            #pragma unroll
            for (int i = 0; i < 8; i++) {
                const int idx = tid + i * 128;
                const int row = idx >> 3;
                const int ch  = idx & 7;
                const uint32_t byte = (uint32_t)row * 128 + (uint32_t)ch * 16;
                cp_async_16(stgA + SW128(byte), &A[(size_t)(bm + row) * K + k0 + ch * 8]);
            }
            #pragma unroll
            for (int i = 0; i < 8; i++) {
                const int idx = tid + i * 128;
                const int row = idx >> 3;
                const int ch  = idx & 7;
                const uint32_t byte = (uint32_t)row * 128 + (uint32_t)ch * 16;
                cp_async_16(stgB + SW128(byte), &Bt[(size_t)(bn + row) * K + k0 + ch * 8]);
            }
            CP_COMMIT();
        };

        float acc[4][8][4];
        #pragma unroll
        for (int mt = 0; mt < 4; mt++)
            #pragma unroll
            for (int nt = 0; nt < 8; nt++)
                #pragma unroll
                for (int i = 0; i < 4; i++) acc[mt][nt][i] = 0.f;

        issue_stage(0);
        issue_stage(1);

        for (int it = 0; it < ntiles; it++) {
            if (it + 1 < ntiles) CP_WAIT(1); else CP_WAIT(0);
            __syncthreads();
            if (it + 2 < ntiles) issue_stage(it + 2);

            const uint32_t stgA = smem_base + (uint32_t)(it % NST8) * STG8;
            const uint32_t stgB = stgA + AST8;

            #pragma unroll
            for (int kk = 0; kk < 4; kk++) {
                const uint32_t offA = ((uint32_t)kk * 32 + colA) ^ xr;
                const uint32_t offB = ((uint32_t)kk * 32 + colB) ^ xr;
                uint32_t af[4][4], bf[8][2];
                #pragma unroll
                for (int mt = 0; mt < 4; mt++)
                    ldsm4(af[mt], stgA + relA[mt] + offA);
                #pragma unroll
                for (int p = 0; p < 4; p++) {
                    uint32_t bq[4];
                    ldsm4(bq, stgB + relB[p] + offB);
                    bf[2 * p][0]     = bq[0];
                    bf[2 * p][1]     = bq[1];
                    bf[2 * p + 1][0] = bq[2];
                    bf[2 * p + 1][1] = bq[3];
                }
                #pragma unroll
                for (int mt = 0; mt < 4; mt++)
                    #pragma unroll
                    for (int nt = 0; nt < 8; nt++)
                        mma_f16(acc[mt][nt], af[mt], bf[nt]);
            }
        }

        #pragma unroll
        for (int mt = 0; mt < 4; mt++) {
            const int row0 = bm + warp_m * 64 + mt * 16 + g;
            #pragma unroll
            for (int nt = 0; nt < 8; nt++) {
                const int col = bn + warp_n * 64 + nt * 8 + 2 * l4;
                store2(acc[mt][nt][0], acc[mt][nt][1], &C[(size_t)row0 * N + col]);
                store2(acc[mt][nt][2], acc[mt][nt][3], &C[(size_t)(row0 + 8) * N + col]);
            }
        }
    }
}

// ---------------------------------------------------------------------------
// FP16 flash attention v6 (round-15/16 validated).
// ---------------------------------------------------------------------------
#define BQA 64
#define KTA 64
#define MASKVAL -3.0e38f
#define QSTRH  152
#define Q_BYTES  (64 * QSTRH * 2)
#define K_BYTES  16384u
#define V_BYTES  18432u
#define OFF_K0   ((uint32_t)Q_BYTES)
#define OFF_K1   (OFF_K0 + K_BYTES)
#define OFF_V0   (OFF_K1 + K_BYTES)
#define OFF_V1   (OFF_V0 + V_BYTES)
#define ATT_SMEM (OFF_V1 + V_BYTES)

__global__ void __launch_bounds__(128, 2) attn_f16_v6(
    const __half* __restrict__ q16, const __half* __restrict__ k16,
    const __half* __restrict__ vT, __half* __restrict__ out)
{
    extern __shared__ uint32_t smem[];
    uint32_t smb;
    asm("{ .reg .u64 t; cvta.to.shared.u64 t, %1; cvt.u32.u64 %0, t; }"
        : "=r"(smb) : "l"(smem));
    __half* Qsh = (__half*)smem;

    const int tid  = threadIdx.x;
    const int warp = tid >> 5;
    const int lane = tid & 31;
    const int g    = lane >> 2;
    const int l4   = lane & 3;
    const int r    = lane & 7;
    const int qq   = lane >> 3;
    const int b    = blockIdx.z;
    const int h    = blockIdx.y;
    const int q0   = blockIdx.x * BQA;
    const int gkv  = h >> 2;

    for (int idx = tid; idx < 64 * 16; idx += 128) {
        const int rr = idx >> 4, c8 = idx & 15;
        *(uint4*)&Qsh[rr * QSTRH + c8 * 8] =
            *(const uint4*)&q16[(size_t)(b * SS + q0 + rr) * (HH * DD) + h * DD + c8 * 8];
    }
    __syncthreads();
    uint32_t qf[8][4];
    {
        const int lr = warp * 16;
        #pragma unroll
        for (int kk = 0; kk < 8; kk++) {
            qf[kk][0] = *(const uint32_t*)&Qsh[(lr + g)     * QSTRH + kk * 16 + 2 * l4];
            qf[kk][1] = *(const uint32_t*)&Qsh[(lr + g + 8) * QSTRH + kk * 16 + 2 * l4];
            qf[kk][2] = *(const uint32_t*)&Qsh[(lr + g)     * QSTRH + kk * 16 + 8 + 2 * l4];
            qf[kk][3] = *(const uint32_t*)&Qsh[(lr + g + 8) * QSTRH + kk * 16 + 8 + 2 * l4];
        }
    }
    __syncthreads();

    const int js    = max(0, q0 - WINW);
    const int ntile = (q0 + BQA - js) >> 6;

    const uint32_t xr = (uint32_t)r << 4;
    uint32_t relK[4];
    #pragma unroll
    for (int p = 0; p < 4; p++)
        relK[p] = (uint32_t)(p * 16 + r + (qq >> 1) * 8) * 128;
    const uint32_t colK = (uint32_t)(qq & 1) * 16;

    auto issue_tile = [&](int t) {
        const int kt0 = js + t * KTA;
        const uint32_t kb = smb + (t & 1 ? OFF_K1 : OFF_K0);
        const uint32_t vb = smb + (t & 1 ? OFF_V1 : OFF_V0);
        #pragma unroll
        for (int i = 0; i < 8; i++) {
            const int idx = tid + i * 128;
            const int key = idx >> 4, c = idx & 15;
            const uint32_t byte = (uint32_t)((c >> 3) * 64 + key) * 128 + (uint32_t)(c & 7) * 16;
            cp_async_16(kb + SW128(byte),
                &k16[((size_t)(b * SS + kt0 + key) * KVH + gkv) * DD + c * 8]);
        }
        #pragma unroll
        for (int i = 0; i < 8; i++) {
            const int idx = tid + i * 128;
            const int d = idx >> 3, cc = idx & 7;
            cp_async_16(vb + (uint32_t)(d * 144 + cc * 16),
                &vT[((size_t)(b * KVH + gkv) * DD + d) * SS + kt0 + cc * 8]);
        }
        CP_COMMIT();
    };

    float o[16][4];
    #pragma unroll
    for (int dt = 0; dt < 16; dt++)
        #pragma unroll
        for (int i = 0; i < 4; i++) o[dt][i] = 0.f;
    float m_a = -1e30f, m_b = -1e30f, l_a = 0.f, l_b = 0.f;

    const int i_lo = q0 + warp * 16;
    const int i_a  = i_lo + g;
    const int i_b  = i_a + 8;

    issue_tile(0);

    for (int t = 0; t < ntile; t++) {
        CP_WAIT(0);
        __syncthreads();
        if (t + 1 < ntile) issue_tile(t + 1);

        const int kt0 = js + t * KTA;
        const uint32_t kb = smb + (t & 1 ? OFF_K1 : OFF_K0);
        const uint32_t vb = smb + (t & 1 ? OFF_V1 : OFF_V0);

        float s[8][4];
        #pragma unroll
        for (int nt = 0; nt < 8; nt++)
            #pragma unroll
            for (int i = 0; i < 4; i++) s[nt][i] = 0.f;

        #pragma unroll
        for (int kk = 0; kk < 8; kk++) {
            const uint32_t rowb = kb + (uint32_t)(kk >> 2) * (64 * 128);
            const uint32_t offK = ((uint32_t)(kk & 3) * 32 + colK) ^ xr;
            uint32_t bf[8][2];
            #pragma unroll
            for (int p = 0; p < 4; p++) {
                uint32_t bq[4];
                ldsm4(bq, rowb + relK[p] + offK);
                bf[2*p][0] = bq[0]; bf[2*p][1] = bq[1];
                bf[2*p+1][0] = bq[2]; bf[2*p+1][1] = bq[3];
            }
            #pragma unroll
            for (int nt = 0; nt < 8; nt++)
                mma_f16(s[nt], qf[kk], bf[nt]);
        }

        #pragma unroll
        for (int nt = 0; nt < 8; nt++) {
            const int j0 = kt0 + nt * 8;
            const bool allvalid = (j0 + 7 <= i_lo) && (i_lo + 15 - j0 < WINW);
            if (!allvalid) {
                const int ja = j0 + 2 * l4, jb = ja + 1;
                if (!(ja <= i_a && i_a - ja < WINW)) s[nt][0] = MASKVAL;
                if (!(jb <= i_a && i_a - jb < WINW)) s[nt][1] = MASKVAL;
                if (!(ja <= i_b && i_b - ja < WINW)) s[nt][2] = MASKVAL;
                if (!(jb <= i_b && i_b - jb < WINW)) s[nt][3] = MASKVAL;
            }
        }

        float ta = MASKVAL, tb = MASKVAL;
        #pragma unroll
        for (int nt = 0; nt < 8; nt++) {
            ta = fmaxf(ta, fmaxf(s[nt][0], s[nt][1]));
            tb = fmaxf(tb, fmaxf(s[nt][2], s[nt][3]));
        }
        ta = fmaxf(ta, __shfl_xor_sync(0xffffffffu, ta, 1));
        ta = fmaxf(ta, __shfl_xor_sync(0xffffffffu, ta, 2));
        tb = fmaxf(tb, __shfl_xor_sync(0xffffffffu, tb, 1));
        tb = fmaxf(tb, __shfl_xor_sync(0xffffffffu, tb, 2));

        const float mna = fmaxf(m_a, ta);
        const float mnb = fmaxf(m_b, tb);
        const float alpha_a = __expf(m_a - mna);
        const float alpha_b = __expf(m_b - mnb);
        m_a = mna; m_b = mnb;

        float ra = 0.f, rb = 0.f;
        #pragma unroll
        for (int nt = 0; nt < 8; nt++) {
            s[nt][0] = __expf(s[nt][0] - m_a);
            s[nt][1] = __expf(s[nt][1] - m_a);
            s[nt][2] = __expf(s[nt][2] - m_b);
            s[nt][3] = __expf(s[nt][3] - m_b);
            ra += s[nt][0] + s[nt][1];
            rb += s[nt][2] + s[nt][3];
        }
        ra += __shfl_xor_sync(0xffffffffu, ra, 1);
        ra += __shfl_xor_sync(0xffffffffu, ra, 2);
        rb += __shfl_xor_sync(0xffffffffu, rb, 1);
        rb += __shfl_xor_sync(0xffffffffu, rb, 2);
        l_a = l_a * alpha_a + ra;
        l_b = l_b * alpha_b + rb;

        #pragma unroll
        for (int dt = 0; dt < 16; dt++) {
            o[dt][0] *= alpha_a; o[dt][1] *= alpha_a;
            o[dt][2] *= alpha_b; o[dt][3] *= alpha_b;
        }

        #pragma unroll
        for (int kk = 0; kk < 4; kk++) {
            uint32_t ap[4];
            ap[0] = pack2h(s[2*kk][0],   s[2*kk][1]);
            ap[1] = pack2h(s[2*kk][2],   s[2*kk][3]);
            ap[2] = pack2h(s[2*kk+1][0], s[2*kk+1][1]);
            ap[3] = pack2h(s[2*kk+1][2], s[2*kk+1][3]);
            #pragma unroll
            for (int dtp = 0; dtp < 8; dtp++) {
                uint32_t addr = vb + (uint32_t)(dtp * 16 + r + (qq >> 1) * 8) * 144
                                   + (uint32_t)kk * 32 + (uint32_t)(qq & 1) * 16;
                uint32_t bq[4];
                ldsm4(bq, addr);
                uint32_t b0[2] = { bq[0], bq[1] };
                uint32_t b1[2] = { bq[2], bq[3] };
                mma_f16(o[2*dtp],     ap, b0);
                mma_f16(o[2*dtp + 1], ap, b1);
            }
        }
    }

    const float inv_a = 1.0f / l_a;
    const float inv_b = 1.0f / l_b;
    #pragma unroll
    for (int dt = 0; dt < 16; dt++) {
        const int col = h * DD + dt * 8 + 2 * l4;
        *(uint32_t*)&out[(size_t)(b * SS + i_a) * (HH * DD) + col] =
            pack2h(o[dt][0] * inv_a, o[dt][1] * inv_a);
        *(uint32_t*)&out[(size_t)(b * SS + i_b) * (HH * DD) + col] =
            pack2h(o[dt][2] * inv_b, o[dt][3] * inv_b);
    }
}

// ---------------------------------------------------------------------------
extern "C" void kernel_launch(void* const* d_in, const int* in_sizes, int n_in,
                              void* d_out, int out_size)
{
    const float* x     = (const float*)d_in[0];
    const float* w_qkv = (const float*)d_in[1];
    const float* w_o   = (const float*)d_in[2];
    float* out = (float*)d_out;

    __half* qkvh   = nullptr;
    __half* attn_h = nullptr;
    __half* xh     = nullptr;
    __half* wqkvTh = nullptr;
    __half* woTh   = nullptr;
    __half* q16p   = nullptr;
    __half* k16p   = nullptr;
    __half* vTp    = nullptr;
    cudaGetSymbolAddress((void**)&qkvh,   g_qkv_h);
    cudaGetSymbolAddress((void**)&attn_h, g_attn_h);
    cudaGetSymbolAddress((void**)&xh,     g_xh);
    cudaGetSymbolAddress((void**)&wqkvTh, g_wqkvT_h);
    cudaGetSymbolAddress((void**)&woTh,   g_woT_h);
    cudaGetSymbolAddress((void**)&q16p,   g_q16);
    cudaGetSymbolAddress((void**)&k16p,   g_k16);
    cudaGetSymbolAddress((void**)&vTp,    g_vT);

    cudaFuncSetAttribute(gemm_f16_v10<__half>,
                         cudaFuncAttributeMaxDynamicSharedMemorySize, GEMM_SMEM);
    cudaFuncSetAttribute(gemm_f16_v10<float>,
                         cudaFuncAttributeMaxDynamicSharedMemorySize, GEMM_SMEM);
    cudaFuncSetAttribute(attn_f16_v6,
                         cudaFuncAttributeMaxDynamicSharedMemorySize, ATT_SMEM);

    // 0) prep: merged launch
    prep_all<<<PREP_TOTAL, 256>>>(x, xh, w_qkv, wqkvTh, w_o, woTh);

    // 1) QKV projection (persistent, fp16 out)
    gemm_f16_v10<__half><<<GEMM_PERSIST_CTAS, 128, GEMM_SMEM>>>(
        xh, wqkvTh, qkvh, NROWS, QKVW, EE);

    // 2) RoPE + V transpose: merged launch
    postproc<<<POST_TOTAL, 256>>>(qkvh, q16p, k16p, vTp);

    // 3) Flash attention (fp16, 64-key tiles)
    {
        dim3 grid(SS / BQA, HH, BB);
        attn_f16_v6<<<grid, 128, ATT_SMEM>>>(q16p, k16p, vTp, attn_h);
    }
    // 4) Output projection (persistent, fp32 out)
    gemm_f16_v10<float><<<GEMM_PERSIST_CTAS, 128, GEMM_SMEM>>>(
        attn_h, woTh, out, NROWS, EE, EE);
}